// round 8
// baseline (speedup 1.0000x reference)
#include <cuda_runtime.h>
#include <cuda_bf16.h>
#include <cstdint>

#define NN   50000
#define KK   25
#define FF   128
#define TT   256
#define OUTD 128
#define NBLK 148
#define NKTOT 1250000
#define EPSB 1e-3f
#define NTILES (NN / 5)          /* 10000 */
#define ROWS_T 125               /* 5 nodes * 25 */
#define C1NB 100
#define C2NB 196

typedef unsigned long long u64;
typedef unsigned int u32;

// ---------------- smem layout for passB ----------------
#define SM_AHI  0
#define SM_ALO  34816
#define SM_BHI  69632
#define SM_BLO  137216
#define SM_TOTAL 204800
#define ASTR 272
#define BSTR 528
#define ZSTRIDE 130

// ---------------- scratch ----------------
__device__ float d_poolZ[(size_t)NN * TT];
__device__ float d_SW[(size_t)NN * OUTD];
__device__ float d_PW[(size_t)NN * OUTD];
__device__ float d_pBs2[NBLK * 2 * 256];
__device__ float d_pBq2[NBLK * 2 * 256];
__device__ float d_pC1s[C1NB * 256];
__device__ float d_pC1q[C1NB * 256];
__device__ float d_pC2s[C2NB * 256];
__device__ float d_pC2q[C2NB * 256];
__device__ float d_a1[TT], d_c1[TT];
__device__ float d_a2[256], d_c2[256];

// ---------------- helpers ----------------
__device__ __forceinline__ u32 smem_u32(const void* p) {
    u32 a;
    asm("{ .reg .u64 t; cvta.to.shared.u64 t, %1; cvt.u32.u64 %0, t; }" : "=r"(a) : "l"(p));
    return a;
}
__device__ __forceinline__ void cvt_pair(float x, float y, u32& hi, u32& lo) {
    asm("cvt.rn.bf16x2.f32 %0, %1, %2;" : "=r"(hi) : "f"(y), "f"(x));
    float h0 = __uint_as_float(hi << 16);
    float h1 = __uint_as_float(hi & 0xFFFF0000u);
    asm("cvt.rn.bf16x2.f32 %0, %1, %2;" : "=r"(lo) : "f"(y - h1), "f"(x - h0));
}
__device__ __forceinline__ void ldsm4(u32 a, u32& r0, u32& r1, u32& r2, u32& r3) {
    asm volatile("ldmatrix.sync.aligned.m8n8.x4.shared.b16 {%0,%1,%2,%3}, [%4];"
                 : "=r"(r0), "=r"(r1), "=r"(r2), "=r"(r3) : "r"(a));
}
__device__ __forceinline__ void ldsm4t(u32 a, u32& r0, u32& r1, u32& r2, u32& r3) {
    asm volatile("ldmatrix.sync.aligned.m8n8.x4.trans.shared.b16 {%0,%1,%2,%3}, [%4];"
                 : "=r"(r0), "=r"(r1), "=r"(r2), "=r"(r3) : "r"(a));
}
__device__ __forceinline__ void mma16816(float* d, const u32* a, u32 b0, u32 b1) {
    asm volatile(
        "mma.sync.aligned.m16n8k16.row.col.f32.bf16.bf16.f32 "
        "{%0,%1,%2,%3}, {%4,%5,%6,%7}, {%8,%9}, {%0,%1,%2,%3};"
        : "+f"(d[0]), "+f"(d[1]), "+f"(d[2]), "+f"(d[3])
        : "r"(a[0]), "r"(a[1]), "r"(a[2]), "r"(a[3]), "r"(b0), "r"(b1));
}
__device__ __forceinline__ u64 pack2(float lo, float hi) {
    u64 r;
    asm("mov.b64 %0, {%1, %2};" : "=l"(r) : "f"(lo), "f"(hi));
    return r;
}
__device__ __forceinline__ void fma2(u64& acc, u64 a, u64 b) {
    asm("fma.rn.f32x2 %0, %1, %2, %0;" : "+l"(acc) : "l"(a), "l"(b));
}
__device__ __forceinline__ float2 unpack2(u64 v) {
    float lo, hi;
    asm("mov.b64 {%0, %1}, %2;" : "=f"(lo), "=f"(hi) : "l"(v));
    return make_float2(lo, hi);
}

// ================= pass B: HMMA bf16-split GEMM (R6 form, no reg prefetch) =================
__global__ void __launch_bounds__(256, 1)
passB(const float* __restrict__ neigh, const float* __restrict__ Wt,
      const float* __restrict__ g1) {
    extern __shared__ char smem[];
    const u32 sb = smem_u32(smem);
    const int tid = threadIdx.x;
    const int wid = tid >> 5;
    const int lane = tid & 31;
    const int g8 = lane >> 2;
    const int tig = lane & 3;
    const int mwarp = wid & 3;
    const int nwarp = wid >> 2;
    const int m0 = mwarp * 32;
    const int n0 = nwarp * 128;
    float* zbuf = (float*)smem;

    // ---- B = Wt (hi/lo split) into SMEM once ----
    for (int idx = tid; idx < FF * 64; idx += 256) {
        int k = idx >> 6, n4 = idx & 63;
        float4 v = ((const float4*)Wt)[idx];
        uint2 uh, ul;
        cvt_pair(v.x, v.y, uh.x, ul.x);
        cvt_pair(v.z, v.w, uh.y, ul.y);
        *(uint2*)(smem + SM_BHI + k * BSTR + n4 * 8) = uh;
        *(uint2*)(smem + SM_BLO + k * BSTR + n4 * 8) = ul;
    }

    // epilogue tasks for this thread always hit the same column -> hoist g1 sign
    const int mycol = tid & 127;
    const bool g1pos0 = (__ldg(&g1[mycol]) >= 0.f);
    const bool g1pos1 = (__ldg(&g1[128 + mycol]) >= 0.f);

    const int a_row_l = lane & 15;
    const int a_koff  = (lane >> 4) << 3;
    float sAcc[2] = {0.f, 0.f}, qAcc[2] = {0.f, 0.f};

    for (int gt = blockIdx.x; gt < NTILES; gt += NBLK) {
        __syncthreads();

        // ---- convert A tile: 125 rows x 128 f32 -> bf16 hi/lo ----
        const float4* src = (const float4*)(neigh + (size_t)gt * (ROWS_T * FF));
        for (int idx = tid; idx < ROWS_T * 32; idx += 256) {
            float4 v = src[idx];
            int r = idx >> 5, c4 = idx & 31;
            uint2 uh, ul;
            cvt_pair(v.x, v.y, uh.x, ul.x);
            cvt_pair(v.z, v.w, uh.y, ul.y);
            *(uint2*)(smem + SM_AHI + r * ASTR + c4 * 8) = uh;
            *(uint2*)(smem + SM_ALO + r * ASTR + c4 * 8) = ul;
        }
        __syncthreads();

        // ---- MMA mainloop ----
        float acc[2][16][4];
#pragma unroll
        for (int mt = 0; mt < 2; ++mt)
#pragma unroll
            for (int nt = 0; nt < 16; ++nt)
#pragma unroll
                for (int i = 0; i < 4; ++i) acc[mt][nt][i] = 0.f;

#pragma unroll
        for (int s = 0; s < 8; ++s) {
            u32 ah[2][4], al[2][4];
#pragma unroll
            for (int mt = 0; mt < 2; ++mt) {
                u32 off = (u32)((m0 + mt * 16 + a_row_l) * ASTR + (s * 16 + a_koff) * 2);
                ldsm4(sb + SM_AHI + off, ah[mt][0], ah[mt][1], ah[mt][2], ah[mt][3]);
                ldsm4(sb + SM_ALO + off, al[mt][0], al[mt][1], al[mt][2], al[mt][3]);
            }
#pragma unroll
            for (int nt2 = 0; nt2 < 8; ++nt2) {
                u32 bh[4], bl[4];
                u32 boff = (u32)((s * 16 + a_row_l) * BSTR + (n0 + nt2 * 16 + a_koff) * 2);
                ldsm4t(sb + SM_BHI + boff, bh[0], bh[1], bh[2], bh[3]);
                ldsm4t(sb + SM_BLO + boff, bl[0], bl[1], bl[2], bl[3]);
#pragma unroll
                for (int mt = 0; mt < 2; ++mt) {
                    mma16816(acc[mt][nt2 * 2],     ah[mt], bh[0], bh[1]);
                    mma16816(acc[mt][nt2 * 2],     ah[mt], bl[0], bl[1]);
                    mma16816(acc[mt][nt2 * 2],     al[mt], bh[0], bh[1]);
                    mma16816(acc[mt][nt2 * 2 + 1], ah[mt], bh[2], bh[3]);
                    mma16816(acc[mt][nt2 * 2 + 1], ah[mt], bl[2], bl[3]);
                    mma16816(acc[mt][nt2 * 2 + 1], al[mt], bh[2], bh[3]);
                }
            }
        }
        __syncthreads();

        // ---- epilogue: pooled select by sign(g1) + sums ----
#pragma unroll
        for (int h = 0; h < 2; ++h) {
            if (nwarp == h) {
#pragma unroll
                for (int mt = 0; mt < 2; ++mt)
#pragma unroll
                    for (int nt = 0; nt < 16; ++nt) {
                        int row = m0 + mt * 16 + g8;
                        int col = nt * 8 + tig * 2;
                        float2 lo2; lo2.x = acc[mt][nt][0]; lo2.y = acc[mt][nt][1];
                        float2 hi2; hi2.x = acc[mt][nt][2]; hi2.y = acc[mt][nt][3];
                        *(float2*)(zbuf + row * ZSTRIDE + col) = lo2;
                        *(float2*)(zbuf + (row + 8) * ZSTRIDE + col) = hi2;
                    }
            }
            __syncthreads();
            const bool gpos = h ? g1pos1 : g1pos0;
            for (int task = tid; task < 640; task += 256) {
                const int grp = task >> 7;
                const float* zb = zbuf + grp * 25 * ZSTRIDE + mycol;
                float mx = -3.4e38f, mn = 3.4e38f, s = 0.f, q = 0.f;
#pragma unroll
                for (int r = 0; r < 25; ++r) {
                    float v = zb[r * ZSTRIDE];
                    mx = fmaxf(mx, v);
                    mn = fminf(mn, v);
                    s += v;
                    q = fmaf(v, v, q);
                }
                const size_t node = (size_t)(5 * gt + grp);
                d_poolZ[node * TT + h * 128 + mycol] = gpos ? mx : mn;
                sAcc[h] += s;
                qAcc[h] += q;
            }
            __syncthreads();
        }
    }

    {
        const int b = tid >> 7;
#pragma unroll
        for (int h = 0; h < 2; ++h) {
            d_pBs2[blockIdx.x * 512 + b * 256 + h * 128 + mycol] = sAcc[h];
            d_pBq2[blockIdx.x * 512 + b * 256 + h * 128 + mycol] = qAcc[h];
        }
    }
}

// ---------------- stats1: one block per column, tree reduce ----------------
__global__ void __launch_bounds__(128, 1)
stats1(const float* __restrict__ g1, const float* __restrict__ b1) {
    __shared__ double ss[128], qq[128];
    const int c = blockIdx.x;
    const int t = threadIdx.x;
    double s = 0.0, q = 0.0;
    for (int i = t; i < NBLK * 2; i += 128) {
        s += (double)d_pBs2[i * 256 + c];
        q += (double)d_pBq2[i * 256 + c];
    }
    ss[t] = s; qq[t] = q;
    __syncthreads();
#pragma unroll
    for (int w = 64; w >= 1; w >>= 1) {
        if (t < w) { ss[t] += ss[t + w]; qq[t] += qq[t + w]; }
        __syncthreads();
    }
    if (t == 0) {
        const double inv = 1.0 / (double)NKTOT;
        const double m = ss[0] * inv;
        const double var = qq[0] * inv - m * m;
        const float a = g1[c] * rsqrtf((float)var + EPSB);
        d_a1[c] = a;
        d_c1[c] = b1[c] - a * (float)m;
    }
}

// ---------------- merged pass C1+C2 (grid C1NB+C2NB, work-balanced, 4-chain ILP) ----------------
__global__ void __launch_bounds__(256, 1)
passC12(const float* __restrict__ selfn, const float* __restrict__ Ws,
        const float* __restrict__ Wn) {
    __shared__ float sm[4096];
    const int tid = threadIdx.x;
    const int grp = tid >> 7;
    const int j = tid & 127;

    if (blockIdx.x < C1NB) {
        // ===== C1: SW = self @ Ws, node-pairs for 4-chain ILP =====
        const int bid = blockIdx.x;
        u64 w2[64];
#pragma unroll
        for (int i = 0; i < 64; ++i)
            w2[i] = pack2(Ws[(2 * i) * OUTD + j], Ws[(2 * i + 1) * OUTD + j]);

        float s = 0.f, q = 0.f;
        for (int base = bid * 8; base < NN; base += C1NB * 8) {
            __syncthreads();
#pragma unroll
            for (int k = 0; k < 4; ++k)
                sm[tid + k * 256] = selfn[(size_t)base * FF + tid + k * 256];
            __syncthreads();
#pragma unroll
            for (int ndp = 0; ndp < 2; ++ndp) {
                const int r0 = grp * 4 + ndp * 2;
                const ulonglong2* x0 = (const ulonglong2*)(sm + r0 * FF);
                const ulonglong2* x1 = (const ulonglong2*)(sm + (r0 + 1) * FF);
                u64 a0 = 0ull, a1 = 0ull, b0 = 0ull, b1 = 0ull;
#pragma unroll
                for (int i = 0; i < 32; ++i) {
                    ulonglong2 v0 = x0[i];
                    ulonglong2 v1 = x1[i];
                    fma2(a0, v0.x, w2[2 * i]);
                    fma2(a1, v0.y, w2[2 * i + 1]);
                    fma2(b0, v1.x, w2[2 * i]);
                    fma2(b1, v1.y, w2[2 * i + 1]);
                }
                float2 fa = unpack2(a0), fb = unpack2(a1);
                const float z0 = (fa.x + fa.y) + (fb.x + fb.y);
                fa = unpack2(b0); fb = unpack2(b1);
                const float z1 = (fa.x + fa.y) + (fb.x + fb.y);
                d_SW[(size_t)(base + r0) * OUTD + j] = z0;
                d_SW[(size_t)(base + r0 + 1) * OUTD + j] = z1;
                s += z0;
                q = fmaf(z0, z0, q);
                s += z1;
                q = fmaf(z1, z1, q);
            }
        }
        d_pC1s[bid * 256 + tid] = s;
        d_pC1q[bid * 256 + tid] = q;
    } else {
        // ===== C2: PW = (a1*poolZ + c1) @ Wn, node-pairs, affine in weights =====
        const int bid = blockIdx.x - C1NB;
        float* pos = sm;
        float* sred = sm + 2048;
        u64 w2[64];
        float cst = 0.f;
#pragma unroll
        for (int i = 0; i < 64; ++i) {
            const int t0 = grp * 128 + 2 * i;
            const float wa = Wn[t0 * OUTD + j];
            const float wb = Wn[(t0 + 1) * OUTD + j];
            w2[i] = pack2(d_a1[t0] * wa, d_a1[t0 + 1] * wb);
            cst += d_c1[t0] * wa + d_c1[t0 + 1] * wb;
        }

        float s = 0.f, q = 0.f;
        for (int base = bid * 8; base < NN; base += C2NB * 8) {
            __syncthreads();
#pragma unroll
            for (int k = 0; k < 8; ++k)
                pos[k * 256 + tid] = d_poolZ[(size_t)(base + k) * TT + tid];
            __syncthreads();
#pragma unroll
            for (int ndp = 0; ndp < 4; ++ndp) {
                const ulonglong2* x0 = (const ulonglong2*)(pos + (2 * ndp) * TT + grp * 128);
                const ulonglong2* x1 = (const ulonglong2*)(pos + (2 * ndp + 1) * TT + grp * 128);
                u64 a0 = 0ull, a1 = 0ull, b0 = 0ull, b1 = 0ull;
#pragma unroll
                for (int i = 0; i < 32; ++i) {
                    ulonglong2 v0 = x0[i];
                    ulonglong2 v1 = x1[i];
                    fma2(a0, v0.x, w2[2 * i]);
                    fma2(a1, v0.y, w2[2 * i + 1]);
                    fma2(b0, v1.x, w2[2 * i]);
                    fma2(b1, v1.y, w2[2 * i + 1]);
                }
                float2 fa = unpack2(a0), fb = unpack2(a1);
                sred[grp * 1024 + (2 * ndp) * 128 + j] = (fa.x + fa.y) + (fb.x + fb.y) + cst;
                fa = unpack2(b0); fb = unpack2(b1);
                sred[grp * 1024 + (2 * ndp + 1) * 128 + j] = (fa.x + fa.y) + (fb.x + fb.y) + cst;
            }
            __syncthreads();
#pragma unroll
            for (int k = 0; k < 4; ++k) {
                const int o = tid + k * 256;
                const int nd = o >> 7;
                const float v = sred[nd * 128 + j] + sred[1024 + nd * 128 + j];
                d_PW[(size_t)(base + nd) * OUTD + j] = v;
                s += v;
                q = fmaf(v, v, q);
            }
        }
        d_pC2s[bid * 256 + tid] = s;
        d_pC2q[bid * 256 + tid] = q;
    }
}

// ---------------- stats2: one block per concat-column, tree reduce ----------------
__global__ void __launch_bounds__(128, 1)
stats2(const float* __restrict__ g2, const float* __restrict__ b2) {
    __shared__ double ss[128], qq[128];
    const int c = blockIdx.x;
    const int t = threadIdx.x;
    double s = 0.0, q = 0.0;
    if (c < 128) {
        for (int i = t; i < C1NB * 2; i += 128) {
            const int b = i >> 1, off = (i & 1) * 128;
            s += (double)d_pC1s[b * 256 + off + c];
            q += (double)d_pC1q[b * 256 + off + c];
        }
    } else {
        const int jr = c - 128;
        for (int i = t; i < C2NB * 2; i += 128) {
            const int b = i >> 1, off = (i & 1) * 128;
            s += (double)d_pC2s[b * 256 + off + jr];
            q += (double)d_pC2q[b * 256 + off + jr];
        }
    }
    ss[t] = s; qq[t] = q;
    __syncthreads();
#pragma unroll
    for (int w = 64; w >= 1; w >>= 1) {
        if (t < w) { ss[t] += ss[t + w]; qq[t] += qq[t + w]; }
        __syncthreads();
    }
    if (t == 0) {
        const double inv = 1.0 / (double)NN;
        const double m = ss[0] * inv;
        const double var = qq[0] * inv - m * m;
        const float a = g2[c] * rsqrtf((float)var + EPSB);
        d_a2[c] = a;
        d_c2[c] = b2[c] - a * (float)m;
    }
}

// ---------------- pass E: 4 float4 per thread ----------------
__global__ void passE(float* __restrict__ out) {
    const int base = (blockIdx.x * blockDim.x + threadIdx.x) * 4;
#pragma unroll
    for (int u = 0; u < 4; ++u) {
        const int idx = base + u;
        if (idx >= NN * 64) return;
        const int n = idx >> 6;
        const int c4 = idx & 63;
        float4 v;
        if (c4 < 32) v = ((const float4*)d_SW)[(size_t)n * 32 + c4];
        else         v = ((const float4*)d_PW)[(size_t)n * 32 + (c4 - 32)];
        const float4 a = ((const float4*)d_a2)[c4];
        const float4 c = ((const float4*)d_c2)[c4];
        float4 r;
        r.x = fmaxf(0.f, fmaf(a.x, v.x, c.x));
        r.y = fmaxf(0.f, fmaf(a.y, v.y, c.y));
        r.z = fmaxf(0.f, fmaf(a.z, v.z, c.z));
        r.w = fmaxf(0.f, fmaf(a.w, v.w, c.w));
        ((float4*)out)[idx] = r;
    }
}

// ---------------- launch ----------------
extern "C" void kernel_launch(void* const* d_in, const int* in_sizes, int n_in,
                              void* d_out, int out_size) {
    const float* selfn = (const float*)d_in[0];
    const float* neigh = (const float*)d_in[1];
    const float* Wt = (const float*)d_in[3];
    const float* g1 = (const float*)d_in[5];
    const float* b1 = (const float*)d_in[6];
    const float* Wn = (const float*)d_in[7];
    const float* Ws = (const float*)d_in[8];
    const float* g2 = (const float*)d_in[9];
    const float* b2 = (const float*)d_in[10];
    float* out = (float*)d_out;

    static int configured = 0;
    if (!configured) {
        cudaFuncSetAttribute(passB, cudaFuncAttributeMaxDynamicSharedMemorySize, SM_TOTAL);
        configured = 1;
    }

    passB<<<NBLK, 256, SM_TOTAL>>>(neigh, Wt, g1);
    stats1<<<256, 128>>>(g1, b1);
    passC12<<<C1NB + C2NB, 256>>>(selfn, Ws, Wn);
    stats2<<<256, 128>>>(g2, b2);
    passE<<<(NN * 64 + 1023) / 1024, 256>>>(out);
}

// round 9
// speedup vs baseline: 1.4825x; 1.4825x over previous
#include <cuda_runtime.h>
#include <cuda_bf16.h>
#include <cstdint>

#define NN   50000
#define KK   25
#define FF   128
#define TT   256
#define OUTD 128
#define NBLK 148
#define NKTOT 1250000
#define EPSB 1e-3f
#define NTILES (NN / 5)          /* 10000 */
#define ROWS_T 125               /* 5 nodes * 25 */
#define C1NB 100
#define C2NB 196

typedef unsigned long long u64;
typedef unsigned int u32;

// ---------------- smem layout for passB ----------------
#define SM_AHI  0
#define SM_ALO  34816
#define SM_BHI  69632
#define SM_BLO  137216
#define SM_TOTAL 204800
#define ASTR 272
#define BSTR 528
#define ZSTRIDE 130

// ---------------- scratch ----------------
__device__ float d_poolZ[(size_t)NN * TT];
__device__ float d_SW[(size_t)NN * OUTD];
__device__ float d_PW[(size_t)NN * OUTD];
__device__ float d_pBs2[NBLK * 2 * 256];
__device__ float d_pBq2[NBLK * 2 * 256];
__device__ float d_pC1s[C1NB * 256];
__device__ float d_pC1q[C1NB * 256];
__device__ float d_pC2s[C2NB * 256];
__device__ float d_pC2q[C2NB * 256];
__device__ float d_a1[TT], d_c1[TT];
__device__ float d_a2[256], d_c2[256];

// ---------------- helpers ----------------
__device__ __forceinline__ u32 smem_u32(const void* p) {
    u32 a;
    asm("{ .reg .u64 t; cvta.to.shared.u64 t, %1; cvt.u32.u64 %0, t; }" : "=r"(a) : "l"(p));
    return a;
}
__device__ __forceinline__ void cvt_pair(float x, float y, u32& hi, u32& lo) {
    asm("cvt.rn.bf16x2.f32 %0, %1, %2;" : "=r"(hi) : "f"(y), "f"(x));
    float h0 = __uint_as_float(hi << 16);
    float h1 = __uint_as_float(hi & 0xFFFF0000u);
    asm("cvt.rn.bf16x2.f32 %0, %1, %2;" : "=r"(lo) : "f"(y - h1), "f"(x - h0));
}
__device__ __forceinline__ void ldsm4(u32 a, u32& r0, u32& r1, u32& r2, u32& r3) {
    asm volatile("ldmatrix.sync.aligned.m8n8.x4.shared.b16 {%0,%1,%2,%3}, [%4];"
                 : "=r"(r0), "=r"(r1), "=r"(r2), "=r"(r3) : "r"(a));
}
__device__ __forceinline__ void ldsm4t(u32 a, u32& r0, u32& r1, u32& r2, u32& r3) {
    asm volatile("ldmatrix.sync.aligned.m8n8.x4.trans.shared.b16 {%0,%1,%2,%3}, [%4];"
                 : "=r"(r0), "=r"(r1), "=r"(r2), "=r"(r3) : "r"(a));
}
__device__ __forceinline__ void mma16816(float* d, const u32* a, u32 b0, u32 b1) {
    asm volatile(
        "mma.sync.aligned.m16n8k16.row.col.f32.bf16.bf16.f32 "
        "{%0,%1,%2,%3}, {%4,%5,%6,%7}, {%8,%9}, {%0,%1,%2,%3};"
        : "+f"(d[0]), "+f"(d[1]), "+f"(d[2]), "+f"(d[3])
        : "r"(a[0]), "r"(a[1]), "r"(a[2]), "r"(a[3]), "r"(b0), "r"(b1));
}
__device__ __forceinline__ u64 pack2(float lo, float hi) {
    u64 r;
    asm("mov.b64 %0, {%1, %2};" : "=l"(r) : "f"(lo), "f"(hi));
    return r;
}
__device__ __forceinline__ void fma2(u64& acc, u64 a, u64 b) {
    asm("fma.rn.f32x2 %0, %1, %2, %0;" : "+l"(acc) : "l"(a), "l"(b));
}
__device__ __forceinline__ float2 unpack2(u64 v) {
    float lo, hi;
    asm("mov.b64 {%0, %1}, %2;" : "=f"(lo), "=f"(hi) : "l"(v));
    return make_float2(lo, hi);
}

// ================= pass B: HMMA bf16-split GEMM (exact R6 version) =================
__global__ void __launch_bounds__(256, 1)
passB(const float* __restrict__ neigh, const float* __restrict__ Wt,
      const float* __restrict__ g1) {
    extern __shared__ char smem[];
    const u32 sb = smem_u32(smem);
    const int tid = threadIdx.x;
    const int wid = tid >> 5;
    const int lane = tid & 31;
    const int g8 = lane >> 2;
    const int tig = lane & 3;
    const int mwarp = wid & 3;
    const int nwarp = wid >> 2;
    const int m0 = mwarp * 32;
    const int n0 = nwarp * 128;
    float* zbuf = (float*)smem;

    // ---- B = Wt (hi/lo split) into SMEM once ----
    for (int idx = tid; idx < FF * 64; idx += 256) {
        int k = idx >> 6, n4 = idx & 63;
        float4 v = ((const float4*)Wt)[idx];
        uint2 uh, ul;
        cvt_pair(v.x, v.y, uh.x, ul.x);
        cvt_pair(v.z, v.w, uh.y, ul.y);
        *(uint2*)(smem + SM_BHI + k * BSTR + n4 * 8) = uh;
        *(uint2*)(smem + SM_BLO + k * BSTR + n4 * 8) = ul;
    }

    const int a_row_l = lane & 15;
    const int a_koff  = (lane >> 4) << 3;
    float sAcc[2] = {0.f, 0.f}, qAcc[2] = {0.f, 0.f};

    for (int gt = blockIdx.x; gt < NTILES; gt += NBLK) {
        __syncthreads();

        // ---- convert A tile: 125 rows x 128 f32 -> bf16 hi/lo ----
        const float4* src = (const float4*)(neigh + (size_t)gt * (ROWS_T * FF));
        for (int idx = tid; idx < ROWS_T * 32; idx += 256) {
            float4 v = src[idx];
            int r = idx >> 5, c4 = idx & 31;
            uint2 uh, ul;
            cvt_pair(v.x, v.y, uh.x, ul.x);
            cvt_pair(v.z, v.w, uh.y, ul.y);
            *(uint2*)(smem + SM_AHI + r * ASTR + c4 * 8) = uh;
            *(uint2*)(smem + SM_ALO + r * ASTR + c4 * 8) = ul;
        }
        __syncthreads();

        // ---- MMA mainloop ----
        float acc[2][16][4];
#pragma unroll
        for (int mt = 0; mt < 2; ++mt)
#pragma unroll
            for (int nt = 0; nt < 16; ++nt)
#pragma unroll
                for (int i = 0; i < 4; ++i) acc[mt][nt][i] = 0.f;

#pragma unroll
        for (int s = 0; s < 8; ++s) {
            u32 ah[2][4], al[2][4];
#pragma unroll
            for (int mt = 0; mt < 2; ++mt) {
                u32 off = (u32)((m0 + mt * 16 + a_row_l) * ASTR + (s * 16 + a_koff) * 2);
                ldsm4(sb + SM_AHI + off, ah[mt][0], ah[mt][1], ah[mt][2], ah[mt][3]);
                ldsm4(sb + SM_ALO + off, al[mt][0], al[mt][1], al[mt][2], al[mt][3]);
            }
#pragma unroll
            for (int nt2 = 0; nt2 < 8; ++nt2) {
                u32 bh[4], bl[4];
                u32 boff = (u32)((s * 16 + a_row_l) * BSTR + (n0 + nt2 * 16 + a_koff) * 2);
                ldsm4t(sb + SM_BHI + boff, bh[0], bh[1], bh[2], bh[3]);
                ldsm4t(sb + SM_BLO + boff, bl[0], bl[1], bl[2], bl[3]);
#pragma unroll
                for (int mt = 0; mt < 2; ++mt) {
                    mma16816(acc[mt][nt2 * 2],     ah[mt], bh[0], bh[1]);
                    mma16816(acc[mt][nt2 * 2],     ah[mt], bl[0], bl[1]);
                    mma16816(acc[mt][nt2 * 2],     al[mt], bh[0], bh[1]);
                    mma16816(acc[mt][nt2 * 2 + 1], ah[mt], bh[2], bh[3]);
                    mma16816(acc[mt][nt2 * 2 + 1], ah[mt], bl[2], bl[3]);
                    mma16816(acc[mt][nt2 * 2 + 1], al[mt], bh[2], bh[3]);
                }
            }
        }
        __syncthreads();

        // ---- epilogue: pooled select by sign(g1) + sums ----
#pragma unroll
        for (int h = 0; h < 2; ++h) {
            if (nwarp == h) {
#pragma unroll
                for (int mt = 0; mt < 2; ++mt)
#pragma unroll
                    for (int nt = 0; nt < 16; ++nt) {
                        int row = m0 + mt * 16 + g8;
                        int col = nt * 8 + tig * 2;
                        float2 lo2; lo2.x = acc[mt][nt][0]; lo2.y = acc[mt][nt][1];
                        float2 hi2; hi2.x = acc[mt][nt][2]; hi2.y = acc[mt][nt][3];
                        *(float2*)(zbuf + row * ZSTRIDE + col) = lo2;
                        *(float2*)(zbuf + (row + 8) * ZSTRIDE + col) = hi2;
                    }
            }
            __syncthreads();
            for (int task = tid; task < 640; task += 256) {
                const int grp = task >> 7;
                const int col = task & 127;
                const float* zb = zbuf + grp * 25 * ZSTRIDE + col;
                float mx = -3.4e38f, mn = 3.4e38f, s = 0.f, q = 0.f;
#pragma unroll
                for (int r = 0; r < 25; ++r) {
                    float v = zb[r * ZSTRIDE];
                    mx = fmaxf(mx, v);
                    mn = fminf(mn, v);
                    s += v;
                    q = fmaf(v, v, q);
                }
                const size_t node = (size_t)(5 * gt + grp);
                const float g1v = __ldg(&g1[h * 128 + col]);
                d_poolZ[node * TT + h * 128 + col] = (g1v >= 0.f) ? mx : mn;
                sAcc[h] += s;
                qAcc[h] += q;
            }
            __syncthreads();
        }
    }

    {
        const int b = tid >> 7, col = tid & 127;
#pragma unroll
        for (int h = 0; h < 2; ++h) {
            d_pBs2[blockIdx.x * 512 + b * 256 + h * 128 + col] = sAcc[h];
            d_pBq2[blockIdx.x * 512 + b * 256 + h * 128 + col] = qAcc[h];
        }
    }
}

// ---------------- stats1: one block per column, tree reduce ----------------
__global__ void __launch_bounds__(128, 1)
stats1(const float* __restrict__ g1, const float* __restrict__ b1) {
    __shared__ double ss[128], qq[128];
    const int c = blockIdx.x;
    const int t = threadIdx.x;
    double s = 0.0, q = 0.0;
    for (int i = t; i < NBLK * 2; i += 128) {
        s += (double)d_pBs2[i * 256 + c];
        q += (double)d_pBq2[i * 256 + c];
    }
    ss[t] = s; qq[t] = q;
    __syncthreads();
#pragma unroll
    for (int w = 64; w >= 1; w >>= 1) {
        if (t < w) { ss[t] += ss[t + w]; qq[t] += qq[t + w]; }
        __syncthreads();
    }
    if (t == 0) {
        const double inv = 1.0 / (double)NKTOT;
        const double m = ss[0] * inv;
        const double var = qq[0] * inv - m * m;
        const float a = g1[c] * rsqrtf((float)var + EPSB);
        d_a1[c] = a;
        d_c1[c] = b1[c] - a * (float)m;
    }
}

// ---------------- merged pass C1+C2 (grid C1NB+C2NB, work-balanced, 4-chain ILP) ----------------
__global__ void __launch_bounds__(256, 1)
passC12(const float* __restrict__ selfn, const float* __restrict__ Ws,
        const float* __restrict__ Wn) {
    __shared__ float sm[4096];
    const int tid = threadIdx.x;
    const int grp = tid >> 7;
    const int j = tid & 127;

    if (blockIdx.x < C1NB) {
        // ===== C1: SW = self @ Ws, node-pairs for 4-chain ILP =====
        const int bid = blockIdx.x;
        u64 w2[64];
#pragma unroll
        for (int i = 0; i < 64; ++i)
            w2[i] = pack2(Ws[(2 * i) * OUTD + j], Ws[(2 * i + 1) * OUTD + j]);

        float s = 0.f, q = 0.f;
        for (int base = bid * 8; base < NN; base += C1NB * 8) {
            __syncthreads();
#pragma unroll
            for (int k = 0; k < 4; ++k)
                sm[tid + k * 256] = selfn[(size_t)base * FF + tid + k * 256];
            __syncthreads();
#pragma unroll
            for (int ndp = 0; ndp < 2; ++ndp) {
                const int r0 = grp * 4 + ndp * 2;
                const ulonglong2* x0 = (const ulonglong2*)(sm + r0 * FF);
                const ulonglong2* x1 = (const ulonglong2*)(sm + (r0 + 1) * FF);
                u64 a0 = 0ull, a1 = 0ull, b0 = 0ull, b1 = 0ull;
#pragma unroll
                for (int i = 0; i < 32; ++i) {
                    ulonglong2 v0 = x0[i];
                    ulonglong2 v1 = x1[i];
                    fma2(a0, v0.x, w2[2 * i]);
                    fma2(a1, v0.y, w2[2 * i + 1]);
                    fma2(b0, v1.x, w2[2 * i]);
                    fma2(b1, v1.y, w2[2 * i + 1]);
                }
                float2 fa = unpack2(a0), fb = unpack2(a1);
                const float z0 = (fa.x + fa.y) + (fb.x + fb.y);
                fa = unpack2(b0); fb = unpack2(b1);
                const float z1 = (fa.x + fa.y) + (fb.x + fb.y);
                d_SW[(size_t)(base + r0) * OUTD + j] = z0;
                d_SW[(size_t)(base + r0 + 1) * OUTD + j] = z1;
                s += z0;
                q = fmaf(z0, z0, q);
                s += z1;
                q = fmaf(z1, z1, q);
            }
        }
        d_pC1s[bid * 256 + tid] = s;
        d_pC1q[bid * 256 + tid] = q;
    } else {
        // ===== C2: PW = (a1*poolZ + c1) @ Wn, node-pairs, affine in weights =====
        const int bid = blockIdx.x - C1NB;
        float* pos = sm;
        float* sred = sm + 2048;
        u64 w2[64];
        float cst = 0.f;
#pragma unroll
        for (int i = 0; i < 64; ++i) {
            const int t0 = grp * 128 + 2 * i;
            const float wa = Wn[t0 * OUTD + j];
            const float wb = Wn[(t0 + 1) * OUTD + j];
            w2[i] = pack2(d_a1[t0] * wa, d_a1[t0 + 1] * wb);
            cst += d_c1[t0] * wa + d_c1[t0 + 1] * wb;
        }

        float s = 0.f, q = 0.f;
        for (int base = bid * 8; base < NN; base += C2NB * 8) {
            __syncthreads();
#pragma unroll
            for (int k = 0; k < 8; ++k)
                pos[k * 256 + tid] = d_poolZ[(size_t)(base + k) * TT + tid];
            __syncthreads();
#pragma unroll
            for (int ndp = 0; ndp < 4; ++ndp) {
                const ulonglong2* x0 = (const ulonglong2*)(pos + (2 * ndp) * TT + grp * 128);
                const ulonglong2* x1 = (const ulonglong2*)(pos + (2 * ndp + 1) * TT + grp * 128);
                u64 a0 = 0ull, a1 = 0ull, b0 = 0ull, b1 = 0ull;
#pragma unroll
                for (int i = 0; i < 32; ++i) {
                    ulonglong2 v0 = x0[i];
                    ulonglong2 v1 = x1[i];
                    fma2(a0, v0.x, w2[2 * i]);
                    fma2(a1, v0.y, w2[2 * i + 1]);
                    fma2(b0, v1.x, w2[2 * i]);
                    fma2(b1, v1.y, w2[2 * i + 1]);
                }
                float2 fa = unpack2(a0), fb = unpack2(a1);
                sred[grp * 1024 + (2 * ndp) * 128 + j] = (fa.x + fa.y) + (fb.x + fb.y) + cst;
                fa = unpack2(b0); fb = unpack2(b1);
                sred[grp * 1024 + (2 * ndp + 1) * 128 + j] = (fa.x + fa.y) + (fb.x + fb.y) + cst;
            }
            __syncthreads();
#pragma unroll
            for (int k = 0; k < 4; ++k) {
                const int o = tid + k * 256;
                const int nd = o >> 7;
                const float v = sred[nd * 128 + j] + sred[1024 + nd * 128 + j];
                d_PW[(size_t)(base + nd) * OUTD + j] = v;
                s += v;
                q = fmaf(v, v, q);
            }
        }
        d_pC2s[bid * 256 + tid] = s;
        d_pC2q[bid * 256 + tid] = q;
    }
}

// ---------------- stats2: one block per concat-column, tree reduce ----------------
__global__ void __launch_bounds__(128, 1)
stats2(const float* __restrict__ g2, const float* __restrict__ b2) {
    __shared__ double ss[128], qq[128];
    const int c = blockIdx.x;
    const int t = threadIdx.x;
    double s = 0.0, q = 0.0;
    if (c < 128) {
        for (int i = t; i < C1NB * 2; i += 128) {
            const int b = i >> 1, off = (i & 1) * 128;
            s += (double)d_pC1s[b * 256 + off + c];
            q += (double)d_pC1q[b * 256 + off + c];
        }
    } else {
        const int jr = c - 128;
        for (int i = t; i < C2NB * 2; i += 128) {
            const int b = i >> 1, off = (i & 1) * 128;
            s += (double)d_pC2s[b * 256 + off + jr];
            q += (double)d_pC2q[b * 256 + off + jr];
        }
    }
    ss[t] = s; qq[t] = q;
    __syncthreads();
#pragma unroll
    for (int w = 64; w >= 1; w >>= 1) {
        if (t < w) { ss[t] += ss[t + w]; qq[t] += qq[t + w]; }
        __syncthreads();
    }
    if (t == 0) {
        const double inv = 1.0 / (double)NN;
        const double m = ss[0] * inv;
        const double var = qq[0] * inv - m * m;
        const float a = g2[c] * rsqrtf((float)var + EPSB);
        d_a2[c] = a;
        d_c2[c] = b2[c] - a * (float)m;
    }
}

// ---------------- pass E: 4 float4 per thread ----------------
__global__ void passE(float* __restrict__ out) {
    const int base = (blockIdx.x * blockDim.x + threadIdx.x) * 4;
#pragma unroll
    for (int u = 0; u < 4; ++u) {
        const int idx = base + u;
        if (idx >= NN * 64) return;
        const int n = idx >> 6;
        const int c4 = idx & 63;
        float4 v;
        if (c4 < 32) v = ((const float4*)d_SW)[(size_t)n * 32 + c4];
        else         v = ((const float4*)d_PW)[(size_t)n * 32 + (c4 - 32)];
        const float4 a = ((const float4*)d_a2)[c4];
        const float4 c = ((const float4*)d_c2)[c4];
        float4 r;
        r.x = fmaxf(0.f, fmaf(a.x, v.x, c.x));
        r.y = fmaxf(0.f, fmaf(a.y, v.y, c.y));
        r.z = fmaxf(0.f, fmaf(a.z, v.z, c.z));
        r.w = fmaxf(0.f, fmaf(a.w, v.w, c.w));
        ((float4*)out)[idx] = r;
    }
}

// ---------------- launch ----------------
extern "C" void kernel_launch(void* const* d_in, const int* in_sizes, int n_in,
                              void* d_out, int out_size) {
    const float* selfn = (const float*)d_in[0];
    const float* neigh = (const float*)d_in[1];
    const float* Wt = (const float*)d_in[3];
    const float* g1 = (const float*)d_in[5];
    const float* b1 = (const float*)d_in[6];
    const float* Wn = (const float*)d_in[7];
    const float* Ws = (const float*)d_in[8];
    const float* g2 = (const float*)d_in[9];
    const float* b2 = (const float*)d_in[10];
    float* out = (float*)d_out;

    static int configured = 0;
    if (!configured) {
        cudaFuncSetAttribute(passB, cudaFuncAttributeMaxDynamicSharedMemorySize, SM_TOTAL);
        configured = 1;
    }

    passB<<<NBLK, 256, SM_TOTAL>>>(neigh, Wt, g1);
    stats1<<<256, 128>>>(g1, b1);
    passC12<<<C1NB + C2NB, 256>>>(selfn, Ws, Wn);
    stats2<<<256, 128>>>(g2, b2);
    passE<<<(NN * 64 + 1023) / 1024, 256>>>(out);
}

// round 10
// speedup vs baseline: 1.9734x; 1.3312x over previous
#include <cuda_runtime.h>
#include <cuda_fp16.h>
#include <cstdint>

#define NN   50000
#define KK   25
#define FF   128
#define TT   256
#define OUTD 128
#define NBLK 148
#define NKTOT 1250000
#define EPSB 1e-3f
#define NTILES (NN / 5)          /* 10000 */
#define ROWS_T 125               /* 5 nodes * 25 */
#define C1NB 100
#define C2NB 196
#define NSTG4 4000               /* 125*128/4 float4s per tile */

typedef unsigned long long u64;
typedef unsigned int u32;

// ---------------- smem layout for passB ----------------
// A hi/lo fp16 tiles (ASTR 272B x 128 rows each), B single fp16 (BSTR 528B x 128),
// staging = raw f32 next tile (64000B). zbuf (128x130 f32) aliases the A region.
#define SM_AHI  0
#define SM_ALO  34816
#define SM_B    69632
#define SM_STG  137216
#define SM_TOTAL (137216 + 64000)   /* 201216 */
#define ASTR 272
#define BSTR 528
#define ZSTRIDE 130

// ---------------- scratch ----------------
__device__ float d_poolZ[(size_t)NN * TT];
__device__ float d_SW[(size_t)NN * OUTD];
__device__ float d_PW[(size_t)NN * OUTD];
__device__ float d_pBs2[NBLK * 2 * 256];
__device__ float d_pBq2[NBLK * 2 * 256];
__device__ float d_pC1s[C1NB * 256];
__device__ float d_pC1q[C1NB * 256];
__device__ float d_pC2s[C2NB * 256];
__device__ float d_pC2q[C2NB * 256];
__device__ float d_a1[TT], d_c1[TT];
__device__ float d_a2[256], d_c2[256];

// ---------------- helpers ----------------
__device__ __forceinline__ u32 smem_u32(const void* p) {
    u32 a;
    asm("{ .reg .u64 t; cvta.to.shared.u64 t, %1; cvt.u32.u64 %0, t; }" : "=r"(a) : "l"(p));
    return a;
}
// fp16 pair convert: hi = {f16(y),f16(x)} packed; lo = packed residuals
__device__ __forceinline__ void cvt_pair_f16(float x, float y, u32& hi, u32& lo) {
    asm("cvt.rn.f16x2.f32 %0, %1, %2;" : "=r"(hi) : "f"(y), "f"(x));
    float h0, h1;
    asm("{ .reg .b16 l, h; mov.b32 {l, h}, %2; cvt.f32.f16 %0, l; cvt.f32.f16 %1, h; }"
        : "=f"(h0), "=f"(h1) : "r"(hi));
    asm("cvt.rn.f16x2.f32 %0, %1, %2;" : "=r"(lo) : "f"(y - h1), "f"(x - h0));
}
__device__ __forceinline__ void ldsm4(u32 a, u32& r0, u32& r1, u32& r2, u32& r3) {
    asm volatile("ldmatrix.sync.aligned.m8n8.x4.shared.b16 {%0,%1,%2,%3}, [%4];"
                 : "=r"(r0), "=r"(r1), "=r"(r2), "=r"(r3) : "r"(a));
}
__device__ __forceinline__ void ldsm4t(u32 a, u32& r0, u32& r1, u32& r2, u32& r3) {
    asm volatile("ldmatrix.sync.aligned.m8n8.x4.trans.shared.b16 {%0,%1,%2,%3}, [%4];"
                 : "=r"(r0), "=r"(r1), "=r"(r2), "=r"(r3) : "r"(a));
}
__device__ __forceinline__ void mma16816h(float* d, const u32* a, u32 b0, u32 b1) {
    asm volatile(
        "mma.sync.aligned.m16n8k16.row.col.f32.f16.f16.f32 "
        "{%0,%1,%2,%3}, {%4,%5,%6,%7}, {%8,%9}, {%0,%1,%2,%3};"
        : "+f"(d[0]), "+f"(d[1]), "+f"(d[2]), "+f"(d[3])
        : "r"(a[0]), "r"(a[1]), "r"(a[2]), "r"(a[3]), "r"(b0), "r"(b1));
}
__device__ __forceinline__ u64 pack2(float lo, float hi) {
    u64 r;
    asm("mov.b64 %0, {%1, %2};" : "=l"(r) : "f"(lo), "f"(hi));
    return r;
}
__device__ __forceinline__ void fma2(u64& acc, u64 a, u64 b) {
    asm("fma.rn.f32x2 %0, %1, %2, %0;" : "+l"(acc) : "l"(a), "l"(b));
}
__device__ __forceinline__ float2 unpack2(u64 v) {
    float lo, hi;
    asm("mov.b64 {%0, %1}, %2;" : "=f"(lo), "=f"(hi) : "l"(v));
    return make_float2(lo, hi);
}
__device__ __forceinline__ void cp_async16(u32 dst, const void* src) {
    asm volatile("cp.async.cg.shared.global [%0], [%1], 16;" :: "r"(dst), "l"(src));
}

// ================= pass B: HMMA fp16 2-term split GEMM + cp.async staging pipeline =================
__global__ void __launch_bounds__(256, 1)
passB(const float* __restrict__ neigh, const float* __restrict__ Wt,
      const float* __restrict__ g1) {
    extern __shared__ char smem[];
    const u32 sb = smem_u32(smem);
    const int tid = threadIdx.x;
    const int wid = tid >> 5;
    const int lane = tid & 31;
    const int g8 = lane >> 2;
    const int tig = lane & 3;
    const int mwarp = wid & 3;
    const int nwarp = wid >> 2;
    const int m0 = mwarp * 32;
    const int n0 = nwarp * 128;
    float* zbuf = (float*)smem;
    const float4* stg4 = (const float4*)(smem + SM_STG);

    // ---- prologue: kick off cp.async for the first tile ----
    {
        const float4* src = (const float4*)(neigh + (size_t)blockIdx.x * (ROWS_T * FF));
#pragma unroll
        for (int u = 0; u < 16; ++u) {
            int idx = tid + u * 256;
            if (idx < NSTG4) cp_async16(sb + SM_STG + idx * 16, src + idx);
        }
        asm volatile("cp.async.commit_group;" ::: "memory");
    }

    // ---- B = fp16(Wt) into SMEM once ----
    for (int idx = tid; idx < FF * 64; idx += 256) {
        int k = idx >> 6, n4 = idx & 63;
        float4 v = ((const float4*)Wt)[idx];
        uint2 uh;
        asm("cvt.rn.f16x2.f32 %0, %1, %2;" : "=r"(uh.x) : "f"(v.y), "f"(v.x));
        asm("cvt.rn.f16x2.f32 %0, %1, %2;" : "=r"(uh.y) : "f"(v.w), "f"(v.z));
        *(uint2*)(smem + SM_B + k * BSTR + n4 * 8) = uh;
    }

    const int a_row_l = lane & 15;
    const int a_koff  = (lane >> 4) << 3;
    float sAcc[2] = {0.f, 0.f}, qAcc[2] = {0.f, 0.f};

    for (int gt = blockIdx.x; gt < NTILES; gt += NBLK) {
        asm volatile("cp.async.wait_group 0;" ::: "memory");
        __syncthreads();

        // ---- convert A tile from staging: f32 -> fp16 hi/lo ----
        for (int idx = tid; idx < NSTG4; idx += 256) {
            float4 v = stg4[idx];
            int r = idx >> 5, c4 = idx & 31;
            uint2 uh, ul;
            cvt_pair_f16(v.x, v.y, uh.x, ul.x);
            cvt_pair_f16(v.z, v.w, uh.y, ul.y);
            *(uint2*)(smem + SM_AHI + r * ASTR + c4 * 8) = uh;
            *(uint2*)(smem + SM_ALO + r * ASTR + c4 * 8) = ul;
        }
        __syncthreads();

        // ---- fire-and-forget prefetch of next tile into staging ----
        {
            const int gn = gt + NBLK;
            if (gn < NTILES) {
                const float4* src = (const float4*)(neigh + (size_t)gn * (ROWS_T * FF));
#pragma unroll
                for (int u = 0; u < 16; ++u) {
                    int idx = tid + u * 256;
                    if (idx < NSTG4) cp_async16(sb + SM_STG + idx * 16, src + idx);
                }
            }
            asm volatile("cp.async.commit_group;" ::: "memory");
        }

        // ---- MMA mainloop: D = Ah*B + Al*B ----
        float acc[2][16][4];
#pragma unroll
        for (int mt = 0; mt < 2; ++mt)
#pragma unroll
            for (int nt = 0; nt < 16; ++nt)
#pragma unroll
                for (int i = 0; i < 4; ++i) acc[mt][nt][i] = 0.f;

#pragma unroll
        for (int s = 0; s < 8; ++s) {
            u32 ah[2][4], al[2][4];
#pragma unroll
            for (int mt = 0; mt < 2; ++mt) {
                u32 off = (u32)((m0 + mt * 16 + a_row_l) * ASTR + (s * 16 + a_koff) * 2);
                ldsm4(sb + SM_AHI + off, ah[mt][0], ah[mt][1], ah[mt][2], ah[mt][3]);
                ldsm4(sb + SM_ALO + off, al[mt][0], al[mt][1], al[mt][2], al[mt][3]);
            }
#pragma unroll
            for (int nt2 = 0; nt2 < 8; ++nt2) {
                u32 bh[4];
                u32 boff = (u32)((s * 16 + a_row_l) * BSTR + (n0 + nt2 * 16 + a_koff) * 2);
                ldsm4t(sb + SM_B + boff, bh[0], bh[1], bh[2], bh[3]);
#pragma unroll
                for (int mt = 0; mt < 2; ++mt) {
                    mma16816h(acc[mt][nt2 * 2],     ah[mt], bh[0], bh[1]);
                    mma16816h(acc[mt][nt2 * 2],     al[mt], bh[0], bh[1]);
                    mma16816h(acc[mt][nt2 * 2 + 1], ah[mt], bh[2], bh[3]);
                    mma16816h(acc[mt][nt2 * 2 + 1], al[mt], bh[2], bh[3]);
                }
            }
        }
        __syncthreads();

        // ---- epilogue: pooled select by sign(g1) + sums (zbuf aliases A) ----
#pragma unroll
        for (int h = 0; h < 2; ++h) {
            if (nwarp == h) {
#pragma unroll
                for (int mt = 0; mt < 2; ++mt)
#pragma unroll
                    for (int nt = 0; nt < 16; ++nt) {
                        int row = m0 + mt * 16 + g8;
                        int col = nt * 8 + tig * 2;
                        float2 lo2; lo2.x = acc[mt][nt][0]; lo2.y = acc[mt][nt][1];
                        float2 hi2; hi2.x = acc[mt][nt][2]; hi2.y = acc[mt][nt][3];
                        *(float2*)(zbuf + row * ZSTRIDE + col) = lo2;
                        *(float2*)(zbuf + (row + 8) * ZSTRIDE + col) = hi2;
                    }
            }
            __syncthreads();
            for (int task = tid; task < 640; task += 256) {
                const int grp = task >> 7;
                const int col = task & 127;
                const float* zb = zbuf + grp * 25 * ZSTRIDE + col;
                float mx = -3.4e38f, mn = 3.4e38f, s = 0.f, q = 0.f;
#pragma unroll
                for (int r = 0; r < 25; ++r) {
                    float v = zb[r * ZSTRIDE];
                    mx = fmaxf(mx, v);
                    mn = fminf(mn, v);
                    s += v;
                    q = fmaf(v, v, q);
                }
                const size_t node = (size_t)(5 * gt + grp);
                const float g1v = __ldg(&g1[h * 128 + col]);
                d_poolZ[node * TT + h * 128 + col] = (g1v >= 0.f) ? mx : mn;
                sAcc[h] += s;
                qAcc[h] += q;
            }
            __syncthreads();
        }
    }

    {
        const int b = tid >> 7, col = tid & 127;
#pragma unroll
        for (int h = 0; h < 2; ++h) {
            d_pBs2[blockIdx.x * 512 + b * 256 + h * 128 + col] = sAcc[h];
            d_pBq2[blockIdx.x * 512 + b * 256 + h * 128 + col] = qAcc[h];
        }
    }
}

// ---------------- stats1: one block per column, tree reduce ----------------
__global__ void __launch_bounds__(128, 1)
stats1(const float* __restrict__ g1, const float* __restrict__ b1) {
    __shared__ double ss[128], qq[128];
    const int c = blockIdx.x;
    const int t = threadIdx.x;
    double s = 0.0, q = 0.0;
    for (int i = t; i < NBLK * 2; i += 128) {
        s += (double)d_pBs2[i * 256 + c];
        q += (double)d_pBq2[i * 256 + c];
    }
    ss[t] = s; qq[t] = q;
    __syncthreads();
#pragma unroll
    for (int w = 64; w >= 1; w >>= 1) {
        if (t < w) { ss[t] += ss[t + w]; qq[t] += qq[t + w]; }
        __syncthreads();
    }
    if (t == 0) {
        const double inv = 1.0 / (double)NKTOT;
        const double m = ss[0] * inv;
        const double var = qq[0] * inv - m * m;
        const float a = g1[c] * rsqrtf((float)var + EPSB);
        d_a1[c] = a;
        d_c1[c] = b1[c] - a * (float)m;
    }
}

// ---------------- merged pass C1+C2 (grid C1NB+C2NB, work-balanced, 4-chain ILP) ----------------
__global__ void __launch_bounds__(256, 1)
passC12(const float* __restrict__ selfn, const float* __restrict__ Ws,
        const float* __restrict__ Wn) {
    __shared__ float sm[4096];
    const int tid = threadIdx.x;
    const int grp = tid >> 7;
    const int j = tid & 127;

    if (blockIdx.x < C1NB) {
        const int bid = blockIdx.x;
        u64 w2[64];
#pragma unroll
        for (int i = 0; i < 64; ++i)
            w2[i] = pack2(Ws[(2 * i) * OUTD + j], Ws[(2 * i + 1) * OUTD + j]);

        float s = 0.f, q = 0.f;
        for (int base = bid * 8; base < NN; base += C1NB * 8) {
            __syncthreads();
#pragma unroll
            for (int k = 0; k < 4; ++k)
                sm[tid + k * 256] = selfn[(size_t)base * FF + tid + k * 256];
            __syncthreads();
#pragma unroll
            for (int ndp = 0; ndp < 2; ++ndp) {
                const int r0 = grp * 4 + ndp * 2;
                const ulonglong2* x0 = (const ulonglong2*)(sm + r0 * FF);
                const ulonglong2* x1 = (const ulonglong2*)(sm + (r0 + 1) * FF);
                u64 a0 = 0ull, a1 = 0ull, b0 = 0ull, b1 = 0ull;
#pragma unroll
                for (int i = 0; i < 32; ++i) {
                    ulonglong2 v0 = x0[i];
                    ulonglong2 v1 = x1[i];
                    fma2(a0, v0.x, w2[2 * i]);
                    fma2(a1, v0.y, w2[2 * i + 1]);
                    fma2(b0, v1.x, w2[2 * i]);
                    fma2(b1, v1.y, w2[2 * i + 1]);
                }
                float2 fa = unpack2(a0), fb = unpack2(a1);
                const float z0 = (fa.x + fa.y) + (fb.x + fb.y);
                fa = unpack2(b0); fb = unpack2(b1);
                const float z1 = (fa.x + fa.y) + (fb.x + fb.y);
                d_SW[(size_t)(base + r0) * OUTD + j] = z0;
                d_SW[(size_t)(base + r0 + 1) * OUTD + j] = z1;
                s += z0;
                q = fmaf(z0, z0, q);
                s += z1;
                q = fmaf(z1, z1, q);
            }
        }
        d_pC1s[bid * 256 + tid] = s;
        d_pC1q[bid * 256 + tid] = q;
    } else {
        const int bid = blockIdx.x - C1NB;
        float* pos = sm;
        float* sred = sm + 2048;
        u64 w2[64];
        float cst = 0.f;
#pragma unroll
        for (int i = 0; i < 64; ++i) {
            const int t0 = grp * 128 + 2 * i;
            const float wa = Wn[t0 * OUTD + j];
            const float wb = Wn[(t0 + 1) * OUTD + j];
            w2[i] = pack2(d_a1[t0] * wa, d_a1[t0 + 1] * wb);
            cst += d_c1[t0] * wa + d_c1[t0 + 1] * wb;
        }

        float s = 0.f, q = 0.f;
        for (int base = bid * 8; base < NN; base += C2NB * 8) {
            __syncthreads();
#pragma unroll
            for (int k = 0; k < 8; ++k)
                pos[k * 256 + tid] = d_poolZ[(size_t)(base + k) * TT + tid];
            __syncthreads();
#pragma unroll
            for (int ndp = 0; ndp < 4; ++ndp) {
                const ulonglong2* x0 = (const ulonglong2*)(pos + (2 * ndp) * TT + grp * 128);
                const ulonglong2* x1 = (const ulonglong2*)(pos + (2 * ndp + 1) * TT + grp * 128);
                u64 a0 = 0ull, a1 = 0ull, b0 = 0ull, b1 = 0ull;
#pragma unroll
                for (int i = 0; i < 32; ++i) {
                    ulonglong2 v0 = x0[i];
                    ulonglong2 v1 = x1[i];
                    fma2(a0, v0.x, w2[2 * i]);
                    fma2(a1, v0.y, w2[2 * i + 1]);
                    fma2(b0, v1.x, w2[2 * i]);
                    fma2(b1, v1.y, w2[2 * i + 1]);
                }
                float2 fa = unpack2(a0), fb = unpack2(a1);
                sred[grp * 1024 + (2 * ndp) * 128 + j] = (fa.x + fa.y) + (fb.x + fb.y) + cst;
                fa = unpack2(b0); fb = unpack2(b1);
                sred[grp * 1024 + (2 * ndp + 1) * 128 + j] = (fa.x + fa.y) + (fb.x + fb.y) + cst;
            }
            __syncthreads();
#pragma unroll
            for (int k = 0; k < 4; ++k) {
                const int o = tid + k * 256;
                const int nd = o >> 7;
                const float v = sred[nd * 128 + j] + sred[1024 + nd * 128 + j];
                d_PW[(size_t)(base + nd) * OUTD + j] = v;
                s += v;
                q = fmaf(v, v, q);
            }
        }
        d_pC2s[bid * 256 + tid] = s;
        d_pC2q[bid * 256 + tid] = q;
    }
}

// ---------------- stats2: one block per concat-column, tree reduce ----------------
__global__ void __launch_bounds__(128, 1)
stats2(const float* __restrict__ g2, const float* __restrict__ b2) {
    __shared__ double ss[128], qq[128];
    const int c = blockIdx.x;
    const int t = threadIdx.x;
    double s = 0.0, q = 0.0;
    if (c < 128) {
        for (int i = t; i < C1NB * 2; i += 128) {
            const int b = i >> 1, off = (i & 1) * 128;
            s += (double)d_pC1s[b * 256 + off + c];
            q += (double)d_pC1q[b * 256 + off + c];
        }
    } else {
        const int jr = c - 128;
        for (int i = t; i < C2NB * 2; i += 128) {
            const int b = i >> 1, off = (i & 1) * 128;
            s += (double)d_pC2s[b * 256 + off + jr];
            q += (double)d_pC2q[b * 256 + off + jr];
        }
    }
    ss[t] = s; qq[t] = q;
    __syncthreads();
#pragma unroll
    for (int w = 64; w >= 1; w >>= 1) {
        if (t < w) { ss[t] += ss[t + w]; qq[t] += qq[t + w]; }
        __syncthreads();
    }
    if (t == 0) {
        const double inv = 1.0 / (double)NN;
        const double m = ss[0] * inv;
        const double var = qq[0] * inv - m * m;
        const float a = g2[c] * rsqrtf((float)var + EPSB);
        d_a2[c] = a;
        d_c2[c] = b2[c] - a * (float)m;
    }
}

// ---------------- pass E: 4 float4 per thread ----------------
__global__ void passE(float* __restrict__ out) {
    const int base = (blockIdx.x * blockDim.x + threadIdx.x) * 4;
#pragma unroll
    for (int u = 0; u < 4; ++u) {
        const int idx = base + u;
        if (idx >= NN * 64) return;
        const int n = idx >> 6;
        const int c4 = idx & 63;
        float4 v;
        if (c4 < 32) v = ((const float4*)d_SW)[(size_t)n * 32 + c4];
        else         v = ((const float4*)d_PW)[(size_t)n * 32 + (c4 - 32)];
        const float4 a = ((const float4*)d_a2)[c4];
        const float4 c = ((const float4*)d_c2)[c4];
        float4 r;
        r.x = fmaxf(0.f, fmaf(a.x, v.x, c.x));
        r.y = fmaxf(0.f, fmaf(a.y, v.y, c.y));
        r.z = fmaxf(0.f, fmaf(a.z, v.z, c.z));
        r.w = fmaxf(0.f, fmaf(a.w, v.w, c.w));
        ((float4*)out)[idx] = r;
    }
}

// ---------------- launch ----------------
extern "C" void kernel_launch(void* const* d_in, const int* in_sizes, int n_in,
                              void* d_out, int out_size) {
    const float* selfn = (const float*)d_in[0];
    const float* neigh = (const float*)d_in[1];
    const float* Wt = (const float*)d_in[3];
    const float* g1 = (const float*)d_in[5];
    const float* b1 = (const float*)d_in[6];
    const float* Wn = (const float*)d_in[7];
    const float* Ws = (const float*)d_in[8];
    const float* g2 = (const float*)d_in[9];
    const float* b2 = (const float*)d_in[10];
    float* out = (float*)d_out;

    static int configured = 0;
    if (!configured) {
        cudaFuncSetAttribute(passB, cudaFuncAttributeMaxDynamicSharedMemorySize, SM_TOTAL);
        configured = 1;
    }

    passB<<<NBLK, 256, SM_TOTAL>>>(neigh, Wt, g1);
    stats1<<<256, 128>>>(g1, b1);
    passC12<<<C1NB + C2NB, 256>>>(selfn, Ws, Wn);
    stats2<<<256, 128>>>(g2, b2);
    passE<<<(NN * 64 + 1023) / 1024, 256>>>(out);
}

// round 11
// speedup vs baseline: 2.4147x; 1.2236x over previous
#include <cuda_runtime.h>
#include <cuda_fp16.h>
#include <cstdint>

#define NN   50000
#define KK   25
#define FF   128
#define TT   256
#define OUTD 128
#define NBLK 148
#define NKTOT 1250000
#define EPSB 1e-3f
#define NTILES (NN / 5)          /* 10000 */
#define ROWS_T 125               /* 5 nodes * 25 */
#define C1NB 100
#define C2NB 196
#define NSTG4 4000               /* 125*128/4 float4s per tile */

typedef unsigned long long u64;
typedef unsigned int u32;

// ---------------- smem layout for passB ----------------
// A fp16 tile (ASTR 272B x 128 rows), B fp16 (BSTR 528B x 128),
// staging = raw f32 next tile. zbuf (128x130 f32) aliases the A region.
#define SM_AHI  0
#define SM_B    69632
#define SM_STG  137216
#define SM_TOTAL (137216 + 64000)   /* 201216 */
#define ASTR 272
#define BSTR 528
#define ZSTRIDE 130

// ---------------- scratch ----------------
__device__ float d_poolZ[(size_t)NN * TT];
__device__ float d_SW[(size_t)NN * OUTD];
__device__ float d_PW[(size_t)NN * OUTD];
__device__ float d_pBs2[NBLK * 2 * 256];
__device__ float d_pBq2[NBLK * 2 * 256];
__device__ float d_pC1s[C1NB * 256];
__device__ float d_pC1q[C1NB * 256];
__device__ float d_pC2s[C2NB * 256];
__device__ float d_pC2q[C2NB * 256];
__device__ float d_a1[TT], d_c1[TT];
__device__ float d_a2[256], d_c2[256];

// ---------------- helpers ----------------
__device__ __forceinline__ u32 smem_u32(const void* p) {
    u32 a;
    asm("{ .reg .u64 t; cvta.to.shared.u64 t, %1; cvt.u32.u64 %0, t; }" : "=r"(a) : "l"(p));
    return a;
}
__device__ __forceinline__ void ldsm4(u32 a, u32& r0, u32& r1, u32& r2, u32& r3) {
    asm volatile("ldmatrix.sync.aligned.m8n8.x4.shared.b16 {%0,%1,%2,%3}, [%4];"
                 : "=r"(r0), "=r"(r1), "=r"(r2), "=r"(r3) : "r"(a));
}
__device__ __forceinline__ void ldsm4t(u32 a, u32& r0, u32& r1, u32& r2, u32& r3) {
    asm volatile("ldmatrix.sync.aligned.m8n8.x4.trans.shared.b16 {%0,%1,%2,%3}, [%4];"
                 : "=r"(r0), "=r"(r1), "=r"(r2), "=r"(r3) : "r"(a));
}
__device__ __forceinline__ void mma16816h(float* d, const u32* a, u32 b0, u32 b1) {
    asm volatile(
        "mma.sync.aligned.m16n8k16.row.col.f32.f16.f16.f32 "
        "{%0,%1,%2,%3}, {%4,%5,%6,%7}, {%8,%9}, {%0,%1,%2,%3};"
        : "+f"(d[0]), "+f"(d[1]), "+f"(d[2]), "+f"(d[3])
        : "r"(a[0]), "r"(a[1]), "r"(a[2]), "r"(a[3]), "r"(b0), "r"(b1));
}
__device__ __forceinline__ u64 pack2(float lo, float hi) {
    u64 r;
    asm("mov.b64 %0, {%1, %2};" : "=l"(r) : "f"(lo), "f"(hi));
    return r;
}
__device__ __forceinline__ void fma2(u64& acc, u64 a, u64 b) {
    asm("fma.rn.f32x2 %0, %1, %2, %0;" : "+l"(acc) : "l"(a), "l"(b));
}
__device__ __forceinline__ float2 unpack2(u64 v) {
    float lo, hi;
    asm("mov.b64 {%0, %1}, %2;" : "=f"(lo), "=f"(hi) : "l"(v));
    return make_float2(lo, hi);
}
__device__ __forceinline__ void cp_async16(u32 dst, const void* src) {
    asm volatile("cp.async.cg.shared.global [%0], [%1], 16;" :: "r"(dst), "l"(src));
}

// ================= pass B: HMMA fp16 single-term GEMM + cp.async staging pipeline =================
__global__ void __launch_bounds__(256, 1)
passB(const float* __restrict__ neigh, const float* __restrict__ Wt,
      const float* __restrict__ g1) {
    extern __shared__ char smem[];
    const u32 sb = smem_u32(smem);
    const int tid = threadIdx.x;
    const int wid = tid >> 5;
    const int lane = tid & 31;
    const int g8 = lane >> 2;
    const int tig = lane & 3;
    const int mwarp = wid & 3;
    const int nwarp = wid >> 2;
    const int m0 = mwarp * 32;
    const int n0 = nwarp * 128;
    float* zbuf = (float*)smem;
    const float4* stg4 = (const float4*)(smem + SM_STG);

    // ---- prologue: kick off cp.async for the first tile ----
    {
        const float4* src = (const float4*)(neigh + (size_t)blockIdx.x * (ROWS_T * FF));
#pragma unroll
        for (int u = 0; u < 16; ++u) {
            int idx = tid + u * 256;
            if (idx < NSTG4) cp_async16(sb + SM_STG + idx * 16, src + idx);
        }
        asm volatile("cp.async.commit_group;" ::: "memory");
    }

    // ---- B = fp16(Wt) into SMEM once ----
    for (int idx = tid; idx < FF * 64; idx += 256) {
        int k = idx >> 6, n4 = idx & 63;
        float4 v = ((const float4*)Wt)[idx];
        uint2 uh;
        asm("cvt.rn.f16x2.f32 %0, %1, %2;" : "=r"(uh.x) : "f"(v.y), "f"(v.x));
        asm("cvt.rn.f16x2.f32 %0, %1, %2;" : "=r"(uh.y) : "f"(v.w), "f"(v.z));
        *(uint2*)(smem + SM_B + k * BSTR + n4 * 8) = uh;
    }

    const int a_row_l = lane & 15;
    const int a_koff  = (lane >> 4) << 3;
    float sAcc[2] = {0.f, 0.f}, qAcc[2] = {0.f, 0.f};

    for (int gt = blockIdx.x; gt < NTILES; gt += NBLK) {
        asm volatile("cp.async.wait_group 0;" ::: "memory");
        __syncthreads();

        // ---- convert A tile from staging: f32 -> fp16 (single term) ----
        for (int idx = tid; idx < NSTG4; idx += 256) {
            float4 v = stg4[idx];
            int r = idx >> 5, c4 = idx & 31;
            uint2 uh;
            asm("cvt.rn.f16x2.f32 %0, %1, %2;" : "=r"(uh.x) : "f"(v.y), "f"(v.x));
            asm("cvt.rn.f16x2.f32 %0, %1, %2;" : "=r"(uh.y) : "f"(v.w), "f"(v.z));
            *(uint2*)(smem + SM_AHI + r * ASTR + c4 * 8) = uh;
        }
        __syncthreads();

        // ---- fire-and-forget prefetch of next tile into staging ----
        {
            const int gn = gt + NBLK;
            if (gn < NTILES) {
                const float4* src = (const float4*)(neigh + (size_t)gn * (ROWS_T * FF));
#pragma unroll
                for (int u = 0; u < 16; ++u) {
                    int idx = tid + u * 256;
                    if (idx < NSTG4) cp_async16(sb + SM_STG + idx * 16, src + idx);
                }
            }
            asm volatile("cp.async.commit_group;" ::: "memory");
        }

        // ---- MMA mainloop: D = A*B ----
        float acc[2][16][4];
#pragma unroll
        for (int mt = 0; mt < 2; ++mt)
#pragma unroll
            for (int nt = 0; nt < 16; ++nt)
#pragma unroll
                for (int i = 0; i < 4; ++i) acc[mt][nt][i] = 0.f;

#pragma unroll
        for (int s = 0; s < 8; ++s) {
            u32 ah[2][4];
#pragma unroll
            for (int mt = 0; mt < 2; ++mt) {
                u32 off = (u32)((m0 + mt * 16 + a_row_l) * ASTR + (s * 16 + a_koff) * 2);
                ldsm4(sb + SM_AHI + off, ah[mt][0], ah[mt][1], ah[mt][2], ah[mt][3]);
            }
#pragma unroll
            for (int nt2 = 0; nt2 < 8; ++nt2) {
                u32 bh[4];
                u32 boff = (u32)((s * 16 + a_row_l) * BSTR + (n0 + nt2 * 16 + a_koff) * 2);
                ldsm4t(sb + SM_B + boff, bh[0], bh[1], bh[2], bh[3]);
#pragma unroll
                for (int mt = 0; mt < 2; ++mt) {
                    mma16816h(acc[mt][nt2 * 2],     ah[mt], bh[0], bh[1]);
                    mma16816h(acc[mt][nt2 * 2 + 1], ah[mt], bh[2], bh[3]);
                }
            }
        }
        __syncthreads();

        // ---- epilogue: pooled select by sign(g1) + sums (zbuf aliases A) ----
#pragma unroll
        for (int h = 0; h < 2; ++h) {
            if (nwarp == h) {
#pragma unroll
                for (int mt = 0; mt < 2; ++mt)
#pragma unroll
                    for (int nt = 0; nt < 16; ++nt) {
                        int row = m0 + mt * 16 + g8;
                        int col = nt * 8 + tig * 2;
                        float2 lo2; lo2.x = acc[mt][nt][0]; lo2.y = acc[mt][nt][1];
                        float2 hi2; hi2.x = acc[mt][nt][2]; hi2.y = acc[mt][nt][3];
                        *(float2*)(zbuf + row * ZSTRIDE + col) = lo2;
                        *(float2*)(zbuf + (row + 8) * ZSTRIDE + col) = hi2;
                    }
            }
            __syncthreads();
            for (int task = tid; task < 640; task += 256) {
                const int grp = task >> 7;
                const int col = task & 127;
                const float* zb = zbuf + grp * 25 * ZSTRIDE + col;
                float mx = -3.4e38f, mn = 3.4e38f, s = 0.f, q = 0.f;
#pragma unroll
                for (int r = 0; r < 25; ++r) {
                    float v = zb[r * ZSTRIDE];
                    mx = fmaxf(mx, v);
                    mn = fminf(mn, v);
                    s += v;
                    q = fmaf(v, v, q);
                }
                const size_t node = (size_t)(5 * gt + grp);
                const float g1v = __ldg(&g1[h * 128 + col]);
                d_poolZ[node * TT + h * 128 + col] = (g1v >= 0.f) ? mx : mn;
                sAcc[h] += s;
                qAcc[h] += q;
            }
            __syncthreads();
        }
    }

    {
        const int b = tid >> 7, col = tid & 127;
#pragma unroll
        for (int h = 0; h < 2; ++h) {
            d_pBs2[blockIdx.x * 512 + b * 256 + h * 128 + col] = sAcc[h];
            d_pBq2[blockIdx.x * 512 + b * 256 + h * 128 + col] = qAcc[h];
        }
    }
}

// ---------------- stats1: one block per column, tree reduce ----------------
__global__ void __launch_bounds__(128, 1)
stats1(const float* __restrict__ g1, const float* __restrict__ b1) {
    __shared__ double ss[128], qq[128];
    const int c = blockIdx.x;
    const int t = threadIdx.x;
    double s = 0.0, q = 0.0;
    for (int i = t; i < NBLK * 2; i += 128) {
        s += (double)d_pBs2[i * 256 + c];
        q += (double)d_pBq2[i * 256 + c];
    }
    ss[t] = s; qq[t] = q;
    __syncthreads();
#pragma unroll
    for (int w = 64; w >= 1; w >>= 1) {
        if (t < w) { ss[t] += ss[t + w]; qq[t] += qq[t + w]; }
        __syncthreads();
    }
    if (t == 0) {
        const double inv = 1.0 / (double)NKTOT;
        const double m = ss[0] * inv;
        const double var = qq[0] * inv - m * m;
        const float a = g1[c] * rsqrtf((float)var + EPSB);
        d_a1[c] = a;
        d_c1[c] = b1[c] - a * (float)m;
    }
}

// ---------------- merged pass C1+C2 (grid C1NB+C2NB, work-balanced, 4-chain ILP) ----------------
__global__ void __launch_bounds__(256, 1)
passC12(const float* __restrict__ selfn, const float* __restrict__ Ws,
        const float* __restrict__ Wn) {
    __shared__ float sm[4096];
    const int tid = threadIdx.x;
    const int grp = tid >> 7;
    const int j = tid & 127;

    if (blockIdx.x < C1NB) {
        const int bid = blockIdx.x;
        u64 w2[64];
#pragma unroll
        for (int i = 0; i < 64; ++i)
            w2[i] = pack2(Ws[(2 * i) * OUTD + j], Ws[(2 * i + 1) * OUTD + j]);

        float s = 0.f, q = 0.f;
        for (int base = bid * 8; base < NN; base += C1NB * 8) {
            __syncthreads();
#pragma unroll
            for (int k = 0; k < 4; ++k)
                sm[tid + k * 256] = selfn[(size_t)base * FF + tid + k * 256];
            __syncthreads();
#pragma unroll
            for (int ndp = 0; ndp < 2; ++ndp) {
                const int r0 = grp * 4 + ndp * 2;
                const ulonglong2* x0 = (const ulonglong2*)(sm + r0 * FF);
                const ulonglong2* x1 = (const ulonglong2*)(sm + (r0 + 1) * FF);
                u64 a0 = 0ull, a1 = 0ull, b0 = 0ull, b1 = 0ull;
#pragma unroll
                for (int i = 0; i < 32; ++i) {
                    ulonglong2 v0 = x0[i];
                    ulonglong2 v1 = x1[i];
                    fma2(a0, v0.x, w2[2 * i]);
                    fma2(a1, v0.y, w2[2 * i + 1]);
                    fma2(b0, v1.x, w2[2 * i]);
                    fma2(b1, v1.y, w2[2 * i + 1]);
                }
                float2 fa = unpack2(a0), fb = unpack2(a1);
                const float z0 = (fa.x + fa.y) + (fb.x + fb.y);
                fa = unpack2(b0); fb = unpack2(b1);
                const float z1 = (fa.x + fa.y) + (fb.x + fb.y);
                d_SW[(size_t)(base + r0) * OUTD + j] = z0;
                d_SW[(size_t)(base + r0 + 1) * OUTD + j] = z1;
                s += z0;
                q = fmaf(z0, z0, q);
                s += z1;
                q = fmaf(z1, z1, q);
            }
        }
        d_pC1s[bid * 256 + tid] = s;
        d_pC1q[bid * 256 + tid] = q;
    } else {
        const int bid = blockIdx.x - C1NB;
        float* pos = sm;
        float* sred = sm + 2048;
        u64 w2[64];
        float cst = 0.f;
#pragma unroll
        for (int i = 0; i < 64; ++i) {
            const int t0 = grp * 128 + 2 * i;
            const float wa = Wn[t0 * OUTD + j];
            const float wb = Wn[(t0 + 1) * OUTD + j];
            w2[i] = pack2(d_a1[t0] * wa, d_a1[t0 + 1] * wb);
            cst += d_c1[t0] * wa + d_c1[t0 + 1] * wb;
        }

        float s = 0.f, q = 0.f;
        for (int base = bid * 8; base < NN; base += C2NB * 8) {
            __syncthreads();
#pragma unroll
            for (int k = 0; k < 8; ++k)
                pos[k * 256 + tid] = d_poolZ[(size_t)(base + k) * TT + tid];
            __syncthreads();
#pragma unroll
            for (int ndp = 0; ndp < 4; ++ndp) {
                const ulonglong2* x0 = (const ulonglong2*)(pos + (2 * ndp) * TT + grp * 128);
                const ulonglong2* x1 = (const ulonglong2*)(pos + (2 * ndp + 1) * TT + grp * 128);
                u64 a0 = 0ull, a1 = 0ull, b0 = 0ull, b1 = 0ull;
#pragma unroll
                for (int i = 0; i < 32; ++i) {
                    ulonglong2 v0 = x0[i];
                    ulonglong2 v1 = x1[i];
                    fma2(a0, v0.x, w2[2 * i]);
                    fma2(a1, v0.y, w2[2 * i + 1]);
                    fma2(b0, v1.x, w2[2 * i]);
                    fma2(b1, v1.y, w2[2 * i + 1]);
                }
                float2 fa = unpack2(a0), fb = unpack2(a1);
                sred[grp * 1024 + (2 * ndp) * 128 + j] = (fa.x + fa.y) + (fb.x + fb.y) + cst;
                fa = unpack2(b0); fb = unpack2(b1);
                sred[grp * 1024 + (2 * ndp + 1) * 128 + j] = (fa.x + fa.y) + (fb.x + fb.y) + cst;
            }
            __syncthreads();
#pragma unroll
            for (int k = 0; k < 4; ++k) {
                const int o = tid + k * 256;
                const int nd = o >> 7;
                const float v = sred[nd * 128 + j] + sred[1024 + nd * 128 + j];
                d_PW[(size_t)(base + nd) * OUTD + j] = v;
                s += v;
                q = fmaf(v, v, q);
            }
        }
        d_pC2s[bid * 256 + tid] = s;
        d_pC2q[bid * 256 + tid] = q;
    }
}

// ---------------- stats2: one block per concat-column, tree reduce ----------------
__global__ void __launch_bounds__(128, 1)
stats2(const float* __restrict__ g2, const float* __restrict__ b2) {
    __shared__ double ss[128], qq[128];
    const int c = blockIdx.x;
    const int t = threadIdx.x;
    double s = 0.0, q = 0.0;
    if (c < 128) {
        for (int i = t; i < C1NB * 2; i += 128) {
            const int b = i >> 1, off = (i & 1) * 128;
            s += (double)d_pC1s[b * 256 + off + c];
            q += (double)d_pC1q[b * 256 + off + c];
        }
    } else {
        const int jr = c - 128;
        for (int i = t; i < C2NB * 2; i += 128) {
            const int b = i >> 1, off = (i & 1) * 128;
            s += (double)d_pC2s[b * 256 + off + jr];
            q += (double)d_pC2q[b * 256 + off + jr];
        }
    }
    ss[t] = s; qq[t] = q;
    __syncthreads();
#pragma unroll
    for (int w = 64; w >= 1; w >>= 1) {
        if (t < w) { ss[t] += ss[t + w]; qq[t] += qq[t + w]; }
        __syncthreads();
    }
    if (t == 0) {
        const double inv = 1.0 / (double)NN;
        const double m = ss[0] * inv;
        const double var = qq[0] * inv - m * m;
        const float a = g2[c] * rsqrtf((float)var + EPSB);
        d_a2[c] = a;
        d_c2[c] = b2[c] - a * (float)m;
    }
}

// ---------------- pass E: 4 float4 per thread ----------------
__global__ void passE(float* __restrict__ out) {
    const int base = (blockIdx.x * blockDim.x + threadIdx.x) * 4;
#pragma unroll
    for (int u = 0; u < 4; ++u) {
        const int idx = base + u;
        if (idx >= NN * 64) return;
        const int n = idx >> 6;
        const int c4 = idx & 63;
        float4 v;
        if (c4 < 32) v = ((const float4*)d_SW)[(size_t)n * 32 + c4];
        else         v = ((const float4*)d_PW)[(size_t)n * 32 + (c4 - 32)];
        const float4 a = ((const float4*)d_a2)[c4];
        const float4 c = ((const float4*)d_c2)[c4];
        float4 r;
        r.x = fmaxf(0.f, fmaf(a.x, v.x, c.x));
        r.y = fmaxf(0.f, fmaf(a.y, v.y, c.y));
        r.z = fmaxf(0.f, fmaf(a.z, v.z, c.z));
        r.w = fmaxf(0.f, fmaf(a.w, v.w, c.w));
        ((float4*)out)[idx] = r;
    }
}

// ---------------- launch ----------------
extern "C" void kernel_launch(void* const* d_in, const int* in_sizes, int n_in,
                              void* d_out, int out_size) {
    const float* selfn = (const float*)d_in[0];
    const float* neigh = (const float*)d_in[1];
    const float* Wt = (const float*)d_in[3];
    const float* g1 = (const float*)d_in[5];
    const float* b1 = (const float*)d_in[6];
    const float* Wn = (const float*)d_in[7];
    const float* Ws = (const float*)d_in[8];
    const float* g2 = (const float*)d_in[9];
    const float* b2 = (const float*)d_in[10];
    float* out = (float*)d_out;

    static int configured = 0;
    if (!configured) {
        cudaFuncSetAttribute(passB, cudaFuncAttributeMaxDynamicSharedMemorySize, SM_TOTAL);
        configured = 1;
    }

    passB<<<NBLK, 256, SM_TOTAL>>>(neigh, Wt, g1);
    stats1<<<256, 128>>>(g1, b1);
    passC12<<<C1NB + C2NB, 256>>>(selfn, Ws, Wn);
    stats2<<<256, 128>>>(g2, b2);
    passE<<<(NN * 64 + 1023) / 1024, 256>>>(out);
}

// round 12
// speedup vs baseline: 3.2266x; 1.3362x over previous
#include <cuda_runtime.h>
#include <cuda_fp16.h>
#include <cstdint>

#define NN   50000
#define KK   25
#define FF   128
#define TT   256
#define OUTD 128
#define NBLK 148
#define NKTOT 1250000
#define EPSB 1e-3f
#define NTILES (NN / 5)          /* 10000 */
#define ROWS_T 125               /* 5 nodes * 25 */
#define C1NB 100
#define C2NB 196
#define NSTG4 4000               /* 125*128/4 float4s per tile */

typedef unsigned long long u64;
typedef unsigned int u32;

// ---------------- smem layout for passB ----------------
// A fp16 tile (ASTR 272B x 128 rows), B fp16 (BSTR 528B x 128),
// staging = raw f32 next tile. zbuf fp16 (128 x 264 halfs) aliases the A region.
#define SM_AHI  0
#define SM_B    69632
#define SM_STG  137216
#define SM_TOTAL (137216 + 64000)   /* 201216 */
#define ASTR 272
#define BSTR 528
#define ZHSTR 264                   /* halfs per zbuf row (528 B) */

// ---------------- scratch ----------------
__device__ float d_poolZ[(size_t)NN * TT];
__device__ float d_SW[(size_t)NN * OUTD];
__device__ float d_PW[(size_t)NN * OUTD];
__device__ float d_pBs2[NBLK * 256];
__device__ float d_pBq2[NBLK * 256];
__device__ float d_pC1s[C1NB * 256];
__device__ float d_pC1q[C1NB * 256];
__device__ float d_pC2s[C2NB * 256];
__device__ float d_pC2q[C2NB * 256];
__device__ float d_a1[TT], d_c1[TT];
__device__ float d_a2[256], d_c2[256];

// ---------------- helpers ----------------
__device__ __forceinline__ u32 smem_u32(const void* p) {
    u32 a;
    asm("{ .reg .u64 t; cvta.to.shared.u64 t, %1; cvt.u32.u64 %0, t; }" : "=r"(a) : "l"(p));
    return a;
}
__device__ __forceinline__ void ldsm4(u32 a, u32& r0, u32& r1, u32& r2, u32& r3) {
    asm volatile("ldmatrix.sync.aligned.m8n8.x4.shared.b16 {%0,%1,%2,%3}, [%4];"
                 : "=r"(r0), "=r"(r1), "=r"(r2), "=r"(r3) : "r"(a));
}
__device__ __forceinline__ void ldsm4t(u32 a, u32& r0, u32& r1, u32& r2, u32& r3) {
    asm volatile("ldmatrix.sync.aligned.m8n8.x4.trans.shared.b16 {%0,%1,%2,%3}, [%4];"
                 : "=r"(r0), "=r"(r1), "=r"(r2), "=r"(r3) : "r"(a));
}
__device__ __forceinline__ void mma16816h(float* d, const u32* a, u32 b0, u32 b1) {
    asm volatile(
        "mma.sync.aligned.m16n8k16.row.col.f32.f16.f16.f32 "
        "{%0,%1,%2,%3}, {%4,%5,%6,%7}, {%8,%9}, {%0,%1,%2,%3};"
        : "+f"(d[0]), "+f"(d[1]), "+f"(d[2]), "+f"(d[3])
        : "r"(a[0]), "r"(a[1]), "r"(a[2]), "r"(a[3]), "r"(b0), "r"(b1));
}
__device__ __forceinline__ u64 pack2(float lo, float hi) {
    u64 r;
    asm("mov.b64 %0, {%1, %2};" : "=l"(r) : "f"(lo), "f"(hi));
    return r;
}
__device__ __forceinline__ void fma2(u64& acc, u64 a, u64 b) {
    asm("fma.rn.f32x2 %0, %1, %2, %0;" : "+l"(acc) : "l"(a), "l"(b));
}
__device__ __forceinline__ float2 unpack2(u64 v) {
    float lo, hi;
    asm("mov.b64 {%0, %1}, %2;" : "=f"(lo), "=f"(hi) : "l"(v));
    return make_float2(lo, hi);
}
__device__ __forceinline__ void cp_async16(u32 dst, const void* src) {
    asm volatile("cp.async.cg.shared.global [%0], [%1], 16;" :: "r"(dst), "l"(src));
}
#define CP_COMMIT() asm volatile("cp.async.commit_group;" ::: "memory")
#define CP_WAIT0()  asm volatile("cp.async.wait_group 0;" ::: "memory")

// ================= pass B: HMMA fp16 GEMM + cp.async pipeline + fp16 single-pass epilogue =================
__global__ void __launch_bounds__(256, 1)
passB(const float* __restrict__ neigh, const float* __restrict__ Wt,
      const float* __restrict__ g1) {
    extern __shared__ char smem[];
    const u32 sb = smem_u32(smem);
    const int tid = threadIdx.x;
    const int lane = tid & 31;
    const int wid = tid >> 5;
    const int g8 = lane >> 2;
    const int tig = lane & 3;
    const int mwarp = wid & 3;
    const int nwarp = wid >> 2;
    const int m0 = mwarp * 32;
    const int n0 = nwarp * 128;
    const float4* stg4 = (const float4*)(smem + SM_STG);

    // ---- prologue: kick off cp.async for the first tile ----
    {
        const float4* src = (const float4*)(neigh + (size_t)blockIdx.x * (ROWS_T * FF));
#pragma unroll
        for (int u = 0; u < 16; ++u) {
            int idx = tid + u * 256;
            if (idx < NSTG4) cp_async16(sb + SM_STG + idx * 16, src + idx);
        }
        CP_COMMIT();
    }

    // ---- B = fp16(Wt) into SMEM once ----
    for (int idx = tid; idx < FF * 64; idx += 256) {
        int k = idx >> 6, n4 = idx & 63;
        float4 v = ((const float4*)Wt)[idx];
        uint2 uh;
        asm("cvt.rn.f16x2.f32 %0, %1, %2;" : "=r"(uh.x) : "f"(v.y), "f"(v.x));
        asm("cvt.rn.f16x2.f32 %0, %1, %2;" : "=r"(uh.y) : "f"(v.w), "f"(v.z));
        *(uint2*)(smem + SM_B + k * BSTR + n4 * 8) = uh;
    }

    const int a_row_l = lane & 15;
    const int a_koff  = (lane >> 4) << 3;
    float sAcc = 0.f, qAcc = 0.f;

    for (int gt = blockIdx.x; gt < NTILES; gt += NBLK) {
        CP_WAIT0();
        __syncthreads();

        // ---- convert A tile from staging: f32 -> fp16 ----
        for (int idx = tid; idx < NSTG4; idx += 256) {
            float4 v = stg4[idx];
            int r = idx >> 5, c4 = idx & 31;
            uint2 uh;
            asm("cvt.rn.f16x2.f32 %0, %1, %2;" : "=r"(uh.x) : "f"(v.y), "f"(v.x));
            asm("cvt.rn.f16x2.f32 %0, %1, %2;" : "=r"(uh.y) : "f"(v.w), "f"(v.z));
            *(uint2*)(smem + SM_AHI + r * ASTR + c4 * 8) = uh;
        }
        __syncthreads();

        // ---- fire-and-forget prefetch of next tile into staging ----
        {
            const int gn = gt + NBLK;
            if (gn < NTILES) {
                const float4* src = (const float4*)(neigh + (size_t)gn * (ROWS_T * FF));
#pragma unroll
                for (int u = 0; u < 16; ++u) {
                    int idx = tid + u * 256;
                    if (idx < NSTG4) cp_async16(sb + SM_STG + idx * 16, src + idx);
                }
            }
            CP_COMMIT();
        }

        // ---- MMA mainloop: D = A*B ----
        float acc[2][16][4];
#pragma unroll
        for (int mt = 0; mt < 2; ++mt)
#pragma unroll
            for (int nt = 0; nt < 16; ++nt)
#pragma unroll
                for (int i = 0; i < 4; ++i) acc[mt][nt][i] = 0.f;

#pragma unroll
        for (int s = 0; s < 8; ++s) {
            u32 ah[2][4];
#pragma unroll
            for (int mt = 0; mt < 2; ++mt) {
                u32 off = (u32)((m0 + mt * 16 + a_row_l) * ASTR + (s * 16 + a_koff) * 2);
                ldsm4(sb + SM_AHI + off, ah[mt][0], ah[mt][1], ah[mt][2], ah[mt][3]);
            }
#pragma unroll
            for (int nt2 = 0; nt2 < 8; ++nt2) {
                u32 bh[4];
                u32 boff = (u32)((s * 16 + a_row_l) * BSTR + (n0 + nt2 * 16 + a_koff) * 2);
                ldsm4t(sb + SM_B + boff, bh[0], bh[1], bh[2], bh[3]);
#pragma unroll
                for (int mt = 0; mt < 2; ++mt) {
                    mma16816h(acc[mt][nt2 * 2],     ah[mt], bh[0], bh[1]);
                    mma16816h(acc[mt][nt2 * 2 + 1], ah[mt], bh[2], bh[3]);
                }
            }
        }
        __syncthreads();

        // ---- single-pass epilogue: all warps pack fp16 into zbuf ----
#pragma unroll
        for (int mt = 0; mt < 2; ++mt)
#pragma unroll
            for (int nt = 0; nt < 16; ++nt) {
                const int row = m0 + mt * 16 + g8;
                const int col = n0 + nt * 8 + tig * 2;
                u32 p0, p1;
                asm("cvt.rn.f16x2.f32 %0, %1, %2;" : "=r"(p0)
                    : "f"(acc[mt][nt][1]), "f"(acc[mt][nt][0]));
                asm("cvt.rn.f16x2.f32 %0, %1, %2;" : "=r"(p1)
                    : "f"(acc[mt][nt][3]), "f"(acc[mt][nt][2]));
                *(u32*)(smem + row * 528 + col * 2) = p0;
                *(u32*)(smem + (row + 8) * 528 + col * 2) = p1;
            }
        __syncthreads();

        // ---- reduce: thread owns column tid across all 5 node-groups ----
        {
            const float g1v = __ldg(&g1[tid]);
            const __half* zc = (const __half*)smem + tid;
#pragma unroll
            for (int grp = 0; grp < 5; ++grp) {
                const __half* zb = zc + grp * 25 * ZHSTR;
                float mx = -3.4e38f, mn = 3.4e38f;
#pragma unroll
                for (int r = 0; r < 25; ++r) {
                    float v = __half2float(zb[r * ZHSTR]);
                    mx = fmaxf(mx, v);
                    mn = fminf(mn, v);
                    sAcc += v;
                    qAcc = fmaf(v, v, qAcc);
                }
                d_poolZ[(size_t)(5 * gt + grp) * TT + tid] = (g1v >= 0.f) ? mx : mn;
            }
        }
        __syncthreads();
    }

    d_pBs2[blockIdx.x * 256 + tid] = sAcc;
    d_pBq2[blockIdx.x * 256 + tid] = qAcc;
}

// ---------------- stats1: one block per column, tree reduce ----------------
__global__ void __launch_bounds__(128, 1)
stats1(const float* __restrict__ g1, const float* __restrict__ b1) {
    __shared__ double ss[128], qq[128];
    const int c = blockIdx.x;
    const int t = threadIdx.x;
    double s = 0.0, q = 0.0;
    for (int i = t; i < NBLK; i += 128) {
        s += (double)d_pBs2[i * 256 + c];
        q += (double)d_pBq2[i * 256 + c];
    }
    ss[t] = s; qq[t] = q;
    __syncthreads();
#pragma unroll
    for (int w = 64; w >= 1; w >>= 1) {
        if (t < w) { ss[t] += ss[t + w]; qq[t] += qq[t + w]; }
        __syncthreads();
    }
    if (t == 0) {
        const double inv = 1.0 / (double)NKTOT;
        const double m = ss[0] * inv;
        const double var = qq[0] * inv - m * m;
        const float a = g1[c] * rsqrtf((float)var + EPSB);
        d_a1[c] = a;
        d_c1[c] = b1[c] - a * (float)m;
    }
}

// ---------------- merged pass C1+C2, cp.async double-buffered ----------------
__global__ void __launch_bounds__(256, 1)
passC12(const float* __restrict__ selfn, const float* __restrict__ Ws,
        const float* __restrict__ Wn) {
    __shared__ float sm[6144];   // C1: 2x1024 bufs; C2: 2x2048 bufs + 2048 sred
    const u32 sb = smem_u32(sm);
    const int tid = threadIdx.x;
    const int grp = tid >> 7;
    const int j = tid & 127;

    if (blockIdx.x < C1NB) {
        // ===== C1: SW = self @ Ws =====
        const int bid = blockIdx.x;
        const int stride = C1NB * 8;
        u64 w2[64];
#pragma unroll
        for (int i = 0; i < 64; ++i)
            w2[i] = pack2(Ws[(2 * i) * OUTD + j], Ws[(2 * i + 1) * OUTD + j]);

        // prologue prefetch: 8 nodes x 128 f32 = 256 float4
        {
            const float4* src = (const float4*)(selfn + (size_t)bid * 8 * FF);
            cp_async16(sb + tid * 16, src + tid);
            CP_COMMIT();
        }
        int cur = 0;
        float s = 0.f, q = 0.f;
        for (int base = bid * 8; base < NN; base += stride) {
            CP_WAIT0();
            __syncthreads();
            {
                const int nb = base + stride;
                if (nb < NN) {
                    const float4* src = (const float4*)(selfn + (size_t)nb * FF);
                    cp_async16(sb + (cur ^ 1) * 4096 + tid * 16, src + tid);
                }
                CP_COMMIT();
            }
            const float* xs = sm + cur * 1024;
#pragma unroll
            for (int ndp = 0; ndp < 2; ++ndp) {
                const int r0 = grp * 4 + ndp * 2;
                const ulonglong2* x0 = (const ulonglong2*)(xs + r0 * FF);
                const ulonglong2* x1 = (const ulonglong2*)(xs + (r0 + 1) * FF);
                u64 a0 = 0ull, a1 = 0ull, b0 = 0ull, b1 = 0ull;
#pragma unroll
                for (int i = 0; i < 32; ++i) {
                    ulonglong2 v0 = x0[i];
                    ulonglong2 v1 = x1[i];
                    fma2(a0, v0.x, w2[2 * i]);
                    fma2(a1, v0.y, w2[2 * i + 1]);
                    fma2(b0, v1.x, w2[2 * i]);
                    fma2(b1, v1.y, w2[2 * i + 1]);
                }
                float2 fa = unpack2(a0), fb = unpack2(a1);
                const float z0 = (fa.x + fa.y) + (fb.x + fb.y);
                fa = unpack2(b0); fb = unpack2(b1);
                const float z1 = (fa.x + fa.y) + (fb.x + fb.y);
                d_SW[(size_t)(base + r0) * OUTD + j] = z0;
                d_SW[(size_t)(base + r0 + 1) * OUTD + j] = z1;
                s += z0;
                q = fmaf(z0, z0, q);
                s += z1;
                q = fmaf(z1, z1, q);
            }
            cur ^= 1;
        }
        d_pC1s[bid * 256 + tid] = s;
        d_pC1q[bid * 256 + tid] = q;
    } else {
        // ===== C2: PW = (a1*poolZ + c1) @ Wn, affine folded into weights =====
        const int bid = blockIdx.x - C1NB;
        const int stride = C2NB * 8;
        float* sred = sm + 4096;
        u64 w2[64];
        float cst = 0.f;
#pragma unroll
        for (int i = 0; i < 64; ++i) {
            const int t0 = grp * 128 + 2 * i;
            const float wa = Wn[t0 * OUTD + j];
            const float wb = Wn[(t0 + 1) * OUTD + j];
            w2[i] = pack2(d_a1[t0] * wa, d_a1[t0 + 1] * wb);
            cst += d_c1[t0] * wa + d_c1[t0 + 1] * wb;
        }

        // prologue prefetch: 8 nodes x 256 f32 = 512 float4
        {
            const float4* src = (const float4*)(d_poolZ + (size_t)bid * 8 * TT);
            cp_async16(sb + tid * 32, src + tid * 2);
            cp_async16(sb + tid * 32 + 16, src + tid * 2 + 1);
            CP_COMMIT();
        }
        int cur = 0;
        float s = 0.f, q = 0.f;
        for (int base = bid * 8; base < NN; base += stride) {
            CP_WAIT0();
            __syncthreads();
            {
                const int nb = base + stride;
                if (nb < NN) {
                    const float4* src = (const float4*)(d_poolZ + (size_t)nb * TT);
                    const u32 dst = sb + (cur ^ 1) * 8192;
                    cp_async16(dst + tid * 32, src + tid * 2);
                    cp_async16(dst + tid * 32 + 16, src + tid * 2 + 1);
                }
                CP_COMMIT();
            }
            const float* pos = sm + cur * 2048;
#pragma unroll
            for (int ndp = 0; ndp < 4; ++ndp) {
                const ulonglong2* x0 = (const ulonglong2*)(pos + (2 * ndp) * TT + grp * 128);
                const ulonglong2* x1 = (const ulonglong2*)(pos + (2 * ndp + 1) * TT + grp * 128);
                u64 a0 = 0ull, a1 = 0ull, b0 = 0ull, b1 = 0ull;
#pragma unroll
                for (int i = 0; i < 32; ++i) {
                    ulonglong2 v0 = x0[i];
                    ulonglong2 v1 = x1[i];
                    fma2(a0, v0.x, w2[2 * i]);
                    fma2(a1, v0.y, w2[2 * i + 1]);
                    fma2(b0, v1.x, w2[2 * i]);
                    fma2(b1, v1.y, w2[2 * i + 1]);
                }
                float2 fa = unpack2(a0), fb = unpack2(a1);
                sred[grp * 1024 + (2 * ndp) * 128 + j] = (fa.x + fa.y) + (fb.x + fb.y) + cst;
                fa = unpack2(b0); fb = unpack2(b1);
                sred[grp * 1024 + (2 * ndp + 1) * 128 + j] = (fa.x + fa.y) + (fb.x + fb.y) + cst;
            }
            __syncthreads();
#pragma unroll
            for (int k = 0; k < 4; ++k) {
                const int o = tid + k * 256;
                const int nd = o >> 7;
                const float v = sred[nd * 128 + j] + sred[1024 + nd * 128 + j];
                d_PW[(size_t)(base + nd) * OUTD + j] = v;
                s += v;
                q = fmaf(v, v, q);
            }
            cur ^= 1;
        }
        d_pC2s[bid * 256 + tid] = s;
        d_pC2q[bid * 256 + tid] = q;
    }
}

// ---------------- stats2: one block per concat-column, tree reduce ----------------
__global__ void __launch_bounds__(128, 1)
stats2(const float* __restrict__ g2, const float* __restrict__ b2) {
    __shared__ double ss[128], qq[128];
    const int c = blockIdx.x;
    const int t = threadIdx.x;
    double s = 0.0, q = 0.0;
    if (c < 128) {
        for (int i = t; i < C1NB * 2; i += 128) {
            const int b = i >> 1, off = (i & 1) * 128;
            s += (double)d_pC1s[b * 256 + off + c];
            q += (double)d_pC1q[b * 256 + off + c];
        }
    } else {
        const int jr = c - 128;
        for (int i = t; i < C2NB * 2; i += 128) {
            const int b = i >> 1, off = (i & 1) * 128;
            s += (double)d_pC2s[b * 256 + off + jr];
            q += (double)d_pC2q[b * 256 + off + jr];
        }
    }
    ss[t] = s; qq[t] = q;
    __syncthreads();
#pragma unroll
    for (int w = 64; w >= 1; w >>= 1) {
        if (t < w) { ss[t] += ss[t + w]; qq[t] += qq[t + w]; }
        __syncthreads();
    }
    if (t == 0) {
        const double inv = 1.0 / (double)NN;
        const double m = ss[0] * inv;
        const double var = qq[0] * inv - m * m;
        const float a = g2[c] * rsqrtf((float)var + EPSB);
        d_a2[c] = a;
        d_c2[c] = b2[c] - a * (float)m;
    }
}

// ---------------- pass E: 4 float4 per thread ----------------
__global__ void passE(float* __restrict__ out) {
    const int base = (blockIdx.x * blockDim.x + threadIdx.x) * 4;
#pragma unroll
    for (int u = 0; u < 4; ++u) {
        const int idx = base + u;
        if (idx >= NN * 64) return;
        const int n = idx >> 6;
        const int c4 = idx & 63;
        float4 v;
        if (c4 < 32) v = ((const float4*)d_SW)[(size_t)n * 32 + c4];
        else         v = ((const float4*)d_PW)[(size_t)n * 32 + (c4 - 32)];
        const float4 a = ((const float4*)d_a2)[c4];
        const float4 c = ((const float4*)d_c2)[c4];
        float4 r;
        r.x = fmaxf(0.f, fmaf(a.x, v.x, c.x));
        r.y = fmaxf(0.f, fmaf(a.y, v.y, c.y));
        r.z = fmaxf(0.f, fmaf(a.z, v.z, c.z));
        r.w = fmaxf(0.f, fmaf(a.w, v.w, c.w));
        ((float4*)out)[idx] = r;
    }
}

// ---------------- launch ----------------
extern "C" void kernel_launch(void* const* d_in, const int* in_sizes, int n_in,
                              void* d_out, int out_size) {
    const float* selfn = (const float*)d_in[0];
    const float* neigh = (const float*)d_in[1];
    const float* Wt = (const float*)d_in[3];
    const float* g1 = (const float*)d_in[5];
    const float* b1 = (const float*)d_in[6];
    const float* Wn = (const float*)d_in[7];
    const float* Ws = (const float*)d_in[8];
    const float* g2 = (const float*)d_in[9];
    const float* b2 = (const float*)d_in[10];
    float* out = (float*)d_out;

    static int configured = 0;
    if (!configured) {
        cudaFuncSetAttribute(passB, cudaFuncAttributeMaxDynamicSharedMemorySize, SM_TOTAL);
        configured = 1;
    }

    passB<<<NBLK, 256, SM_TOTAL>>>(neigh, Wt, g1);
    stats1<<<256, 128>>>(g1, b1);
    passC12<<<C1NB + C2NB, 256>>>(selfn, Ws, Wn);
    stats2<<<256, 128>>>(g2, b2);
    passE<<<(NN * 64 + 1023) / 1024, 256>>>(out);
}

// round 13
// speedup vs baseline: 3.7618x; 1.1659x over previous
#include <cuda_runtime.h>
#include <cuda_fp16.h>
#include <cstdint>

#define NN   50000
#define KK   25
#define FF   128
#define TT   256
#define OUTD 128
#define NBLK 148
#define NKTOT 1250000
#define EPSB 1e-3f
#define NTILES (NN / 5)          /* 10000 */
#define ROWS_T 125               /* 5 nodes * 25 */
#define C1NB 148
#define C2NB 148
#define NSTG4 4000
#define NTL2 391                 /* ceil(50000/128) */

typedef unsigned long long u64;
typedef unsigned int u32;

// ---------------- smem layout for passB ----------------
#define SM_AHI  0
#define SM_B    69632
#define SM_STG  137216
#define SM_TOTAL (137216 + 64000)   /* 201216 */
#define ASTR 272
#define BSTR 528
#define ZHSTR 264

// ---------------- smem layout for passC2h ----------------
#define C2A   0                     /* A fp16: 128 rows x 528B = 67584; zbuf f32 128x132 aliases */
#define C2B   67584                 /* B fp16: 256 rows x 272B = 69632 */
#define C2AC  137216                /* a1/c1: 512 floats */
#define SM2_TOTAL 139264
#define ZST2  132

// ---------------- scratch ----------------
__device__ float d_poolZ[(size_t)NN * TT];
__device__ float d_SW[(size_t)NN * OUTD];
__device__ float d_PW[(size_t)NN * OUTD];
__device__ float d_pBs2[NBLK * 256];
__device__ float d_pBq2[NBLK * 256];
__device__ float d_pC1s[C1NB * 256];
__device__ float d_pC1q[C1NB * 256];
__device__ float d_pC2s[C2NB * 256];
__device__ float d_pC2q[C2NB * 256];
__device__ float d_a1[TT], d_c1[TT];
__device__ float d_a2[256], d_c2[256];

// ---------------- helpers ----------------
__device__ __forceinline__ u32 smem_u32(const void* p) {
    u32 a;
    asm("{ .reg .u64 t; cvta.to.shared.u64 t, %1; cvt.u32.u64 %0, t; }" : "=r"(a) : "l"(p));
    return a;
}
__device__ __forceinline__ void ldsm4(u32 a, u32& r0, u32& r1, u32& r2, u32& r3) {
    asm volatile("ldmatrix.sync.aligned.m8n8.x4.shared.b16 {%0,%1,%2,%3}, [%4];"
                 : "=r"(r0), "=r"(r1), "=r"(r2), "=r"(r3) : "r"(a));
}
__device__ __forceinline__ void ldsm4t(u32 a, u32& r0, u32& r1, u32& r2, u32& r3) {
    asm volatile("ldmatrix.sync.aligned.m8n8.x4.trans.shared.b16 {%0,%1,%2,%3}, [%4];"
                 : "=r"(r0), "=r"(r1), "=r"(r2), "=r"(r3) : "r"(a));
}
__device__ __forceinline__ void mma16816h(float* d, const u32* a, u32 b0, u32 b1) {
    asm volatile(
        "mma.sync.aligned.m16n8k16.row.col.f32.f16.f16.f32 "
        "{%0,%1,%2,%3}, {%4,%5,%6,%7}, {%8,%9}, {%0,%1,%2,%3};"
        : "+f"(d[0]), "+f"(d[1]), "+f"(d[2]), "+f"(d[3])
        : "r"(a[0]), "r"(a[1]), "r"(a[2]), "r"(a[3]), "r"(b0), "r"(b1));
}
__device__ __forceinline__ u64 pack2(float lo, float hi) {
    u64 r;
    asm("mov.b64 %0, {%1, %2};" : "=l"(r) : "f"(lo), "f"(hi));
    return r;
}
__device__ __forceinline__ void fma2(u64& acc, u64 a, u64 b) {
    asm("fma.rn.f32x2 %0, %1, %2, %0;" : "+l"(acc) : "l"(a), "l"(b));
}
__device__ __forceinline__ float2 unpack2(u64 v) {
    float lo, hi;
    asm("mov.b64 {%0, %1}, %2;" : "=f"(lo), "=f"(hi) : "l"(v));
    return make_float2(lo, hi);
}
__device__ __forceinline__ void cp_async16(u32 dst, const void* src) {
    asm volatile("cp.async.cg.shared.global [%0], [%1], 16;" :: "r"(dst), "l"(src));
}
#define CP_COMMIT() asm volatile("cp.async.commit_group;" ::: "memory")
#define CP_WAIT0()  asm volatile("cp.async.wait_group 0;" ::: "memory")

// ================= pass B: byte-identical to R12 (register-cliff rule: untouched) =================
__global__ void __launch_bounds__(256, 1)
passB(const float* __restrict__ neigh, const float* __restrict__ Wt,
      const float* __restrict__ g1) {
    extern __shared__ char smem[];
    const u32 sb = smem_u32(smem);
    const int tid = threadIdx.x;
    const int lane = tid & 31;
    const int wid = tid >> 5;
    const int g8 = lane >> 2;
    const int tig = lane & 3;
    const int mwarp = wid & 3;
    const int nwarp = wid >> 2;
    const int m0 = mwarp * 32;
    const int n0 = nwarp * 128;
    const float4* stg4 = (const float4*)(smem + SM_STG);

    {
        const float4* src = (const float4*)(neigh + (size_t)blockIdx.x * (ROWS_T * FF));
#pragma unroll
        for (int u = 0; u < 16; ++u) {
            int idx = tid + u * 256;
            if (idx < NSTG4) cp_async16(sb + SM_STG + idx * 16, src + idx);
        }
        CP_COMMIT();
    }

    for (int idx = tid; idx < FF * 64; idx += 256) {
        int k = idx >> 6, n4 = idx & 63;
        float4 v = ((const float4*)Wt)[idx];
        uint2 uh;
        asm("cvt.rn.f16x2.f32 %0, %1, %2;" : "=r"(uh.x) : "f"(v.y), "f"(v.x));
        asm("cvt.rn.f16x2.f32 %0, %1, %2;" : "=r"(uh.y) : "f"(v.w), "f"(v.z));
        *(uint2*)(smem + SM_B + k * BSTR + n4 * 8) = uh;
    }

    const int a_row_l = lane & 15;
    const int a_koff  = (lane >> 4) << 3;
    float sAcc = 0.f, qAcc = 0.f;

    for (int gt = blockIdx.x; gt < NTILES; gt += NBLK) {
        CP_WAIT0();
        __syncthreads();

        for (int idx = tid; idx < NSTG4; idx += 256) {
            float4 v = stg4[idx];
            int r = idx >> 5, c4 = idx & 31;
            uint2 uh;
            asm("cvt.rn.f16x2.f32 %0, %1, %2;" : "=r"(uh.x) : "f"(v.y), "f"(v.x));
            asm("cvt.rn.f16x2.f32 %0, %1, %2;" : "=r"(uh.y) : "f"(v.w), "f"(v.z));
            *(uint2*)(smem + SM_AHI + r * ASTR + c4 * 8) = uh;
        }
        __syncthreads();

        {
            const int gn = gt + NBLK;
            if (gn < NTILES) {
                const float4* src = (const float4*)(neigh + (size_t)gn * (ROWS_T * FF));
#pragma unroll
                for (int u = 0; u < 16; ++u) {
                    int idx = tid + u * 256;
                    if (idx < NSTG4) cp_async16(sb + SM_STG + idx * 16, src + idx);
                }
            }
            CP_COMMIT();
        }

        float acc[2][16][4];
#pragma unroll
        for (int mt = 0; mt < 2; ++mt)
#pragma unroll
            for (int nt = 0; nt < 16; ++nt)
#pragma unroll
                for (int i = 0; i < 4; ++i) acc[mt][nt][i] = 0.f;

#pragma unroll
        for (int s = 0; s < 8; ++s) {
            u32 ah[2][4];
#pragma unroll
            for (int mt = 0; mt < 2; ++mt) {
                u32 off = (u32)((m0 + mt * 16 + a_row_l) * ASTR + (s * 16 + a_koff) * 2);
                ldsm4(sb + SM_AHI + off, ah[mt][0], ah[mt][1], ah[mt][2], ah[mt][3]);
            }
#pragma unroll
            for (int nt2 = 0; nt2 < 8; ++nt2) {
                u32 bh[4];
                u32 boff = (u32)((s * 16 + a_row_l) * BSTR + (n0 + nt2 * 16 + a_koff) * 2);
                ldsm4t(sb + SM_B + boff, bh[0], bh[1], bh[2], bh[3]);
#pragma unroll
                for (int mt = 0; mt < 2; ++mt) {
                    mma16816h(acc[mt][nt2 * 2],     ah[mt], bh[0], bh[1]);
                    mma16816h(acc[mt][nt2 * 2 + 1], ah[mt], bh[2], bh[3]);
                }
            }
        }
        __syncthreads();

#pragma unroll
        for (int mt = 0; mt < 2; ++mt)
#pragma unroll
            for (int nt = 0; nt < 16; ++nt) {
                const int row = m0 + mt * 16 + g8;
                const int col = n0 + nt * 8 + tig * 2;
                u32 p0, p1;
                asm("cvt.rn.f16x2.f32 %0, %1, %2;" : "=r"(p0)
                    : "f"(acc[mt][nt][1]), "f"(acc[mt][nt][0]));
                asm("cvt.rn.f16x2.f32 %0, %1, %2;" : "=r"(p1)
                    : "f"(acc[mt][nt][3]), "f"(acc[mt][nt][2]));
                *(u32*)(smem + row * 528 + col * 2) = p0;
                *(u32*)(smem + (row + 8) * 528 + col * 2) = p1;
            }
        __syncthreads();

        {
            const float g1v = __ldg(&g1[tid]);
            const __half* zc = (const __half*)smem + tid;
#pragma unroll
            for (int grp = 0; grp < 5; ++grp) {
                const __half* zb = zc + grp * 25 * ZHSTR;
                float mx = -3.4e38f, mn = 3.4e38f;
#pragma unroll
                for (int r = 0; r < 25; ++r) {
                    float v = __half2float(zb[r * ZHSTR]);
                    mx = fmaxf(mx, v);
                    mn = fminf(mn, v);
                    sAcc += v;
                    qAcc = fmaf(v, v, qAcc);
                }
                d_poolZ[(size_t)(5 * gt + grp) * TT + tid] = (g1v >= 0.f) ? mx : mn;
            }
        }
        __syncthreads();
    }

    d_pBs2[blockIdx.x * 256 + tid] = sAcc;
    d_pBq2[blockIdx.x * 256 + tid] = qAcc;
}

// ---------------- stats1 ----------------
__global__ void __launch_bounds__(128, 1)
stats1(const float* __restrict__ g1, const float* __restrict__ b1) {
    __shared__ double ss[128], qq[128];
    const int c = blockIdx.x;
    const int t = threadIdx.x;
    double s = 0.0, q = 0.0;
    for (int i = t; i < NBLK; i += 128) {
        s += (double)d_pBs2[i * 256 + c];
        q += (double)d_pBq2[i * 256 + c];
    }
    ss[t] = s; qq[t] = q;
    __syncthreads();
#pragma unroll
    for (int w = 64; w >= 1; w >>= 1) {
        if (t < w) { ss[t] += ss[t + w]; qq[t] += qq[t + w]; }
        __syncthreads();
    }
    if (t == 0) {
        const double inv = 1.0 / (double)NKTOT;
        const double m = ss[0] * inv;
        const double var = qq[0] * inv - m * m;
        const float a = g1[c] * rsqrtf((float)var + EPSB);
        d_a1[c] = a;
        d_c1[c] = b1[c] - a * (float)m;
    }
}

// ---------------- pass C1 only: SW = self @ Ws, cp.async double-buffered ----------------
__global__ void __launch_bounds__(256, 1)
passC1(const float* __restrict__ selfn, const float* __restrict__ Ws) {
    __shared__ float sm[2048];
    const u32 sb = smem_u32(sm);
    const int tid = threadIdx.x;
    const int grp = tid >> 7;
    const int j = tid & 127;
    const int bid = blockIdx.x;
    const int stride = C1NB * 8;

    u64 w2[64];
#pragma unroll
    for (int i = 0; i < 64; ++i)
        w2[i] = pack2(Ws[(2 * i) * OUTD + j], Ws[(2 * i + 1) * OUTD + j]);

    {
        const float4* src = (const float4*)(selfn + (size_t)bid * 8 * FF);
        cp_async16(sb + tid * 16, src + tid);
        CP_COMMIT();
    }
    int cur = 0;
    float s = 0.f, q = 0.f;
    for (int base = bid * 8; base < NN; base += stride) {
        CP_WAIT0();
        __syncthreads();
        {
            const int nb = base + stride;
            if (nb < NN) {
                const float4* src = (const float4*)(selfn + (size_t)nb * FF);
                cp_async16(sb + (cur ^ 1) * 4096 + tid * 16, src + tid);
            }
            CP_COMMIT();
        }
        const float* xs = sm + cur * 1024;
#pragma unroll
        for (int ndp = 0; ndp < 2; ++ndp) {
            const int r0 = grp * 4 + ndp * 2;
            const ulonglong2* x0 = (const ulonglong2*)(xs + r0 * FF);
            const ulonglong2* x1 = (const ulonglong2*)(xs + (r0 + 1) * FF);
            u64 a0 = 0ull, a1 = 0ull, b0 = 0ull, b1 = 0ull;
#pragma unroll
            for (int i = 0; i < 32; ++i) {
                ulonglong2 v0 = x0[i];
                ulonglong2 v1 = x1[i];
                fma2(a0, v0.x, w2[2 * i]);
                fma2(a1, v0.y, w2[2 * i + 1]);
                fma2(b0, v1.x, w2[2 * i]);
                fma2(b1, v1.y, w2[2 * i + 1]);
            }
            float2 fa = unpack2(a0), fb = unpack2(a1);
            const float z0 = (fa.x + fa.y) + (fb.x + fb.y);
            fa = unpack2(b0); fb = unpack2(b1);
            const float z1 = (fa.x + fa.y) + (fb.x + fb.y);
            d_SW[(size_t)(base + r0) * OUTD + j] = z0;
            d_SW[(size_t)(base + r0 + 1) * OUTD + j] = z1;
            s += z0;
            q = fmaf(z0, z0, q);
            s += z1;
            q = fmaf(z1, z1, q);
        }
        cur ^= 1;
    }
    d_pC1s[bid * 256 + tid] = s;
    d_pC1q[bid * 256 + tid] = q;
}

// ================= pass C2h: PW = (a1*poolZ + c1) @ Wn via HMMA fp16 =================
__global__ void __launch_bounds__(256, 1)
passC2h(const float* __restrict__ Wn) {
    extern __shared__ char smem[];
    const u32 sb = smem_u32(smem);
    float* a1s = (float*)(smem + C2AC);
    float* c1s = a1s + 256;
    float* zbuf = (float*)smem;
    const int tid = threadIdx.x;
    const int lane = tid & 31;
    const int wid = tid >> 5;
    const int g8 = lane >> 2;
    const int tig = lane & 3;
    const int m0 = (wid & 3) * 32;
    const int n0 = (wid >> 2) * 64;
    const int a_row_l = lane & 15;
    const int a_koff = (lane >> 4) << 3;

    // a1/c1 into smem
    a1s[tid] = d_a1[tid];
    c1s[tid] = d_c1[tid];

    // B = fp16(Wn): 256 k-rows x 128 cols
    for (int idx = tid; idx < 8192; idx += 256) {
        int k = idx >> 5, j4 = idx & 31;
        float4 v = ((const float4*)Wn)[idx];
        uint2 uh;
        asm("cvt.rn.f16x2.f32 %0, %1, %2;" : "=r"(uh.x) : "f"(v.y), "f"(v.x));
        asm("cvt.rn.f16x2.f32 %0, %1, %2;" : "=r"(uh.y) : "f"(v.w), "f"(v.z));
        *(uint2*)(smem + C2B + k * 272 + j4 * 8) = uh;
    }
    __syncthreads();

    float sAcc = 0.f, qAcc = 0.f;

    for (int tile = blockIdx.x; tile < NTL2; tile += C2NB) {
        __syncthreads();   // prev tile's zbuf readers done before A overwrite

        // ---- convert pooled -> A fp16 with BN1 affine folded ----
        for (int idx = tid; idx < 8192; idx += 256) {
            int r = idx >> 6, t4 = idx & 63;
            int node = tile * 128 + r;
            float4 x;
            if (node < NN) {
                float4 v = ((const float4*)(d_poolZ + (size_t)node * TT))[t4];
                float4 a = ((const float4*)a1s)[t4];
                float4 c = ((const float4*)c1s)[t4];
                x.x = fmaf(a.x, v.x, c.x);
                x.y = fmaf(a.y, v.y, c.y);
                x.z = fmaf(a.z, v.z, c.z);
                x.w = fmaf(a.w, v.w, c.w);
            } else {
                x = make_float4(0.f, 0.f, 0.f, 0.f);
            }
            uint2 uh;
            asm("cvt.rn.f16x2.f32 %0, %1, %2;" : "=r"(uh.x) : "f"(x.y), "f"(x.x));
            asm("cvt.rn.f16x2.f32 %0, %1, %2;" : "=r"(uh.y) : "f"(x.w), "f"(x.z));
            *(uint2*)(smem + C2A + r * 528 + t4 * 8) = uh;
        }
        __syncthreads();

        // ---- MMA: 128x128 tile, K=256 ----
        float acc[2][8][4];
#pragma unroll
        for (int mt = 0; mt < 2; ++mt)
#pragma unroll
            for (int nt = 0; nt < 8; ++nt)
#pragma unroll
                for (int i = 0; i < 4; ++i) acc[mt][nt][i] = 0.f;

#pragma unroll
        for (int s = 0; s < 16; ++s) {
            u32 ah[2][4];
#pragma unroll
            for (int mt = 0; mt < 2; ++mt) {
                u32 off = (u32)((m0 + mt * 16 + a_row_l) * 528 + (s * 16 + a_koff) * 2);
                ldsm4(sb + C2A + off, ah[mt][0], ah[mt][1], ah[mt][2], ah[mt][3]);
            }
#pragma unroll
            for (int nt2 = 0; nt2 < 4; ++nt2) {
                u32 bh[4];
                u32 boff = (u32)((s * 16 + a_row_l) * 272 + (n0 + nt2 * 16 + a_koff) * 2);
                ldsm4t(sb + C2B + boff, bh[0], bh[1], bh[2], bh[3]);
#pragma unroll
                for (int mt = 0; mt < 2; ++mt) {
                    mma16816h(acc[mt][nt2 * 2],     ah[mt], bh[0], bh[1]);
                    mma16816h(acc[mt][nt2 * 2 + 1], ah[mt], bh[2], bh[3]);
                }
            }
        }
        __syncthreads();   // A reads done before zbuf (aliases A) writes

        // ---- fragments -> zbuf f32 ----
#pragma unroll
        for (int mt = 0; mt < 2; ++mt)
#pragma unroll
            for (int nt = 0; nt < 8; ++nt) {
                const int row = m0 + mt * 16 + g8;
                const int col = n0 + nt * 8 + tig * 2;
                float2 lo2; lo2.x = acc[mt][nt][0]; lo2.y = acc[mt][nt][1];
                float2 hi2; hi2.x = acc[mt][nt][2]; hi2.y = acc[mt][nt][3];
                *(float2*)(zbuf + row * ZST2 + col) = lo2;
                *(float2*)(zbuf + (row + 8) * ZST2 + col) = hi2;
            }
        __syncthreads();

        // ---- column sums (thread = (half, col)) + coalesced PW writes ----
        {
            const int col = tid & 127;
            const int hh = tid >> 7;
            const int rbase = tile * 128 + hh * 64;
#pragma unroll
            for (int rr = 0; rr < 64; ++rr) {
                if (rbase + rr < NN) {
                    float v = zbuf[(hh * 64 + rr) * ZST2 + col];
                    sAcc += v;
                    qAcc = fmaf(v, v, qAcc);
                }
            }
        }
        for (int idx = tid; idx < 4096; idx += 256) {
            int r = idx >> 5, c4 = idx & 31;
            int grow = tile * 128 + r;
            if (grow < NN)
                ((float4*)(d_PW + (size_t)grow * OUTD))[c4] =
                    *(const float4*)(zbuf + r * ZST2 + c4 * 4);
        }
    }

    d_pC2s[blockIdx.x * 256 + tid] = sAcc;
    d_pC2q[blockIdx.x * 256 + tid] = qAcc;
}

// ---------------- stats2 ----------------
__global__ void __launch_bounds__(128, 1)
stats2(const float* __restrict__ g2, const float* __restrict__ b2) {
    __shared__ double ss[128], qq[128];
    const int c = blockIdx.x;
    const int t = threadIdx.x;
    double s = 0.0, q = 0.0;
    if (c < 128) {
        for (int i = t; i < C1NB * 2; i += 128) {
            const int b = i >> 1, off = (i & 1) * 128;
            s += (double)d_pC1s[b * 256 + off + c];
            q += (double)d_pC1q[b * 256 + off + c];
        }
    } else {
        const int jr = c - 128;
        for (int i = t; i < C2NB * 2; i += 128) {
            const int b = i >> 1, off = (i & 1) * 128;
            s += (double)d_pC2s[b * 256 + off + jr];
            q += (double)d_pC2q[b * 256 + off + jr];
        }
    }
    ss[t] = s; qq[t] = q;
    __syncthreads();
#pragma unroll
    for (int w = 64; w >= 1; w >>= 1) {
        if (t < w) { ss[t] += ss[t + w]; qq[t] += qq[t + w]; }
        __syncthreads();
    }
    if (t == 0) {
        const double inv = 1.0 / (double)NN;
        const double m = ss[0] * inv;
        const double var = qq[0] * inv - m * m;
        const float a = g2[c] * rsqrtf((float)var + EPSB);
        d_a2[c] = a;
        d_c2[c] = b2[c] - a * (float)m;
    }
}

// ---------------- pass E ----------------
__global__ void passE(float* __restrict__ out) {
    const int base = (blockIdx.x * blockDim.x + threadIdx.x) * 4;
#pragma unroll
    for (int u = 0; u < 4; ++u) {
        const int idx = base + u;
        if (idx >= NN * 64) return;
        const int n = idx >> 6;
        const int c4 = idx & 63;
        float4 v;
        if (c4 < 32) v = ((const float4*)d_SW)[(size_t)n * 32 + c4];
        else         v = ((const float4*)d_PW)[(size_t)n * 32 + (c4 - 32)];
        const float4 a = ((const float4*)d_a2)[c4];
        const float4 c = ((const float4*)d_c2)[c4];
        float4 r;
        r.x = fmaxf(0.f, fmaf(a.x, v.x, c.x));
        r.y = fmaxf(0.f, fmaf(a.y, v.y, c.y));
        r.z = fmaxf(0.f, fmaf(a.z, v.z, c.z));
        r.w = fmaxf(0.f, fmaf(a.w, v.w, c.w));
        ((float4*)out)[idx] = r;
    }
}

// ---------------- launch ----------------
extern "C" void kernel_launch(void* const* d_in, const int* in_sizes, int n_in,
                              void* d_out, int out_size) {
    const float* selfn = (const float*)d_in[0];
    const float* neigh = (const float*)d_in[1];
    const float* Wt = (const float*)d_in[3];
    const float* g1 = (const float*)d_in[5];
    const float* b1 = (const float*)d_in[6];
    const float* Wn = (const float*)d_in[7];
    const float* Ws = (const float*)d_in[8];
    const float* g2 = (const float*)d_in[9];
    const float* b2 = (const float*)d_in[10];
    float* out = (float*)d_out;

    static int configured = 0;
    if (!configured) {
        cudaFuncSetAttribute(passB, cudaFuncAttributeMaxDynamicSharedMemorySize, SM_TOTAL);
        cudaFuncSetAttribute(passC2h, cudaFuncAttributeMaxDynamicSharedMemorySize, SM2_TOTAL);
        configured = 1;
    }

    passB<<<NBLK, 256, SM_TOTAL>>>(neigh, Wt, g1);
    stats1<<<256, 128>>>(g1, b1);
    passC1<<<C1NB, 256>>>(selfn, Ws);
    passC2h<<<C2NB, 256, SM2_TOTAL>>>(Wn);
    stats2<<<256, 128>>>(g2, b2);
    passE<<<(NN * 64 + 1023) / 1024, 256>>>(out);
}